// round 2
// baseline (speedup 1.0000x reference)
#include <cuda_runtime.h>
#include <cuda_bf16.h>

// ---------------- problem constants ----------------
#define DD 256
#define HH 8
#define HDD 32
#define N_MAX 50048         // 50000 rounded up
#define E_MAX 800000
#define NEG_SLOPE 0.2f

// ---------------- device scratch (no allocation allowed) ----------------
__device__ float    g_xp [N_MAX * DD];   // x @ W
__device__ float    g_asrc[N_MAX * HH];
__device__ float    g_adst[N_MAX * HH];
__device__ unsigned g_menc[N_MAX * HH];  // order-encoded segment max
__device__ float    g_den [N_MAX * HH];  // softmax denominator
__device__ float    g_ex  [E_MAX * HH];  // per-edge exp(e - m)
__device__ float    g_acc [N_MAX * DD];  // aggregation accumulator
__device__ float    g_hn  [N_MAX * DD];  // post-layernorm
__device__ float    g_hid [N_MAX * DD];  // FFN hidden

// order-preserving float <-> uint encoding (monotone for atomicMax)
__device__ __forceinline__ unsigned fenc(float f) {
    unsigned u = __float_as_uint(f);
    return (u & 0x80000000u) ? ~u : (u | 0x80000000u);
}
__device__ __forceinline__ float fdec(unsigned k) {
    return (k & 0x80000000u) ? __uint_as_float(k ^ 0x80000000u)
                             : __uint_as_float(~k);
}
__device__ __forceinline__ float leaky(float v) {
    return v > 0.f ? v : NEG_SLOPE * v;
}

// ---------------- tiled fp32 GEMM: C[M,256] = A[M,256] @ B[256,256] ----------------
template <bool RELU, bool BIAS>
__global__ void gemm64(const float* __restrict__ A, const float* __restrict__ B,
                       const float* __restrict__ bias, float* __restrict__ C, int M) {
    __shared__ float As[64][33];
    __shared__ float Bs[32][65];
    const int tid  = threadIdx.x;              // 256 threads
    const int brow = blockIdx.x * 64;
    const int bcol = blockIdx.y * 64;
    const int tr   = tid >> 4;                 // 0..15
    const int tc   = tid & 15;                 // 0..15
    float acc[4][4] = {};

    for (int k0 = 0; k0 < 256; k0 += 32) {
#pragma unroll
        for (int t = 0; t < 8; t++) {
            int i = tid + t * 256;
            int r = i >> 5, c = i & 31;
            int gr = brow + r;
            As[r][c] = (gr < M) ? A[gr * 256 + k0 + c] : 0.f;
        }
#pragma unroll
        for (int t = 0; t < 8; t++) {
            int i = tid + t * 256;
            int r = i >> 6, c = i & 63;
            Bs[r][c] = B[(k0 + r) * 256 + bcol + c];
        }
        __syncthreads();
#pragma unroll
        for (int kk = 0; kk < 32; kk++) {
            float a[4], b[4];
#pragma unroll
            for (int i = 0; i < 4; i++) a[i] = As[tr * 4 + i][kk];
#pragma unroll
            for (int j = 0; j < 4; j++) b[j] = Bs[kk][tc * 4 + j];
#pragma unroll
            for (int i = 0; i < 4; i++)
#pragma unroll
                for (int j = 0; j < 4; j++)
                    acc[i][j] = fmaf(a[i], b[j], acc[i][j]);
        }
        __syncthreads();
    }
#pragma unroll
    for (int i = 0; i < 4; i++) {
        int gr = brow + tr * 4 + i;
        if (gr >= M) continue;
#pragma unroll
        for (int j = 0; j < 4; j++) {
            int gc = bcol + tc * 4 + j;
            float v = acc[i][j];
            if (BIAS) v += bias[gc];
            if (RELU) v = fmaxf(v, 0.f);
            C[gr * 256 + gc] = v;
        }
    }
}

// ---------------- per-node attention logits + init max with self-loop ----------------
__global__ void node_att(const float* __restrict__ att_src,
                         const float* __restrict__ att_dst, int n) {
    int i = blockIdx.x * blockDim.x + threadIdx.x;
    if (i >= n) return;
    const float* xp = g_xp + i * 256;
#pragma unroll
    for (int h = 0; h < HH; h++) {
        float s = 0.f, d = 0.f;
#pragma unroll
        for (int k = 0; k < HDD; k++) {
            float v = xp[h * HDD + k];
            s = fmaf(v, att_src[h * HDD + k], s);
            d = fmaf(v, att_dst[h * HDD + k], d);
        }
        g_asrc[i * HH + h] = s;
        g_adst[i * HH + h] = d;
        float e = leaky(s + d);          // self-loop logit seeds the max
        g_menc[i * HH + h] = fenc(e);
        g_den [i * HH + h] = 0.f;
    }
}

// ---------------- per-edge segment max (edge_index is int32: JAX x64-disabled) ----------------
__global__ void edge_max(const int* __restrict__ ei, int E) {
    int e = blockIdx.x * blockDim.x + threadIdx.x;
    if (e >= E) return;
    int s = ei[e];
    int d = ei[E + e];
#pragma unroll
    for (int h = 0; h < HH; h++) {
        float v = leaky(g_asrc[s * HH + h] + g_adst[d * HH + h]);
        atomicMax(&g_menc[d * HH + h], fenc(v));
    }
}

// ---------------- per-edge exp + denominator ----------------
__global__ void edge_exp(const int* __restrict__ ei, int E) {
    int e = blockIdx.x * blockDim.x + threadIdx.x;
    if (e >= E) return;
    int s = ei[e];
    int d = ei[E + e];
#pragma unroll
    for (int h = 0; h < HH; h++) {
        float v  = leaky(g_asrc[s * HH + h] + g_adst[d * HH + h]);
        float m  = fdec(g_menc[d * HH + h]);
        float ex = expf(v - m);
        g_ex[e * HH + h] = ex;
        atomicAdd(&g_den[d * HH + h], ex);
    }
}

// ---------------- node: finalize denom with self term, init acc with self message ----------------
__global__ void node_self(int n) {
    int warp = (blockIdx.x * blockDim.x + threadIdx.x) >> 5;
    int lane = threadIdx.x & 31;
    if (warp >= n) return;
    float aval = 0.f;
    if (lane < HH) {
        int idx = warp * HH + lane;
        float se  = leaky(g_asrc[idx] + g_adst[idx]);
        float m   = fdec(g_menc[idx]);
        float exs = expf(se - m);
        float den = g_den[idx] + exs;
        g_den[idx] = den;                    // complete denominator for edge pass
        aval = exs / (den + 1e-16f);
    }
#pragma unroll
    for (int k = 0; k < HH; k++) {
        float alpha = __shfl_sync(0xffffffffu, aval, k);
        int c = k * 32 + lane;
        g_acc[warp * 256 + c] = alpha * g_xp[warp * 256 + c];
    }
}

// ---------------- warp-per-edge scatter aggregation ----------------
__global__ void edge_agg(const int* __restrict__ ei, int E) {
    int warp = (blockIdx.x * blockDim.x + threadIdx.x) >> 5;
    int lane = threadIdx.x & 31;
    if (warp >= E) return;
    int s = ei[warp];
    int d = ei[E + warp];
    float aval = 0.f;
    if (lane < HH)
        aval = g_ex[warp * HH + lane] / (g_den[d * HH + lane] + 1e-16f);
#pragma unroll
    for (int k = 0; k < HH; k++) {
        float alpha = __shfl_sync(0xffffffffu, aval, k);
        int c = k * 32 + lane;
        atomicAdd(&g_acc[d * 256 + c], alpha * g_xp[s * 256 + c]);
    }
}

// ---------------- bias + residual + LayerNorm (block per row) ----------------
__global__ void ln_kernel(const float* __restrict__ x,
                          const float* __restrict__ bias,
                          const float* __restrict__ gamma,
                          const float* __restrict__ beta, int n) {
    int i = blockIdx.x;
    if (i >= n) return;
    int t = threadIdx.x;                      // 256 threads
    __shared__ float sh[8];
    __shared__ float s_mu, s_rstd;

    float r = g_acc[i * 256 + t] + bias[t] + x[i * 256 + t];

    // mean
    float v = r;
#pragma unroll
    for (int o = 16; o; o >>= 1) v += __shfl_down_sync(0xffffffffu, v, o);
    if ((t & 31) == 0) sh[t >> 5] = v;
    __syncthreads();
    if (t == 0) {
        float w = 0.f;
#pragma unroll
        for (int k = 0; k < 8; k++) w += sh[k];
        s_mu = w * (1.0f / 256.0f);
    }
    __syncthreads();
    float c = r - s_mu;

    // variance
    float v2 = c * c;
#pragma unroll
    for (int o = 16; o; o >>= 1) v2 += __shfl_down_sync(0xffffffffu, v2, o);
    __syncthreads();                          // protect sh reuse
    if ((t & 31) == 0) sh[t >> 5] = v2;
    __syncthreads();
    if (t == 0) {
        float w = 0.f;
#pragma unroll
        for (int k = 0; k < 8; k++) w += sh[k];
        s_rstd = rsqrtf(w * (1.0f / 256.0f) + 1e-5f);
    }
    __syncthreads();

    g_hn[i * 256 + t] = c * s_rstd * gamma[t] + beta[t];
}

// ---------------- launch ----------------
extern "C" void kernel_launch(void* const* d_in, const int* in_sizes, int n_in,
                              void* d_out, int out_size) {
    const float* x       = (const float*)d_in[0];
    const int*   ei      = (const int*)d_in[1];   // int32 (JAX x64 disabled)
    // d_in[2] = edge_attr (unused)
    const float* W       = (const float*)d_in[3];
    const float* att_src = (const float*)d_in[4];
    const float* att_dst = (const float*)d_in[5];
    const float* bias    = (const float*)d_in[6];
    const float* ln_g    = (const float*)d_in[7];
    const float* ln_b    = (const float*)d_in[8];
    const float* W1      = (const float*)d_in[9];
    const float* b1      = (const float*)d_in[10];
    const float* W2      = (const float*)d_in[11];
    const float* b2      = (const float*)d_in[12];

    const int n = in_sizes[0] / DD;       // 50000
    const int E = in_sizes[1] / 2;        // 800000

    float *xp, *hn, *hid;
    cudaGetSymbolAddress((void**)&xp,  g_xp);
    cudaGetSymbolAddress((void**)&hn,  g_hn);
    cudaGetSymbolAddress((void**)&hid, g_hid);

    dim3 gg((n + 63) / 64, 4);

    // 1) xp = x @ W
    gemm64<false, false><<<gg, 256>>>(x, W, nullptr, xp, n);
    // 2) attention logits + softmax init
    node_att<<<(n + 255) / 256, 256>>>(att_src, att_dst, n);
    // 3) segment max over edges
    edge_max<<<(E + 255) / 256, 256>>>(ei, E);
    // 4) exp + denominator
    edge_exp<<<(E + 255) / 256, 256>>>(ei, E);
    // 5) finalize denom with self-loop, init accumulator with self message
    node_self<<<(n * 32 + 255) / 256, 256>>>(n);
    // 6) scatter aggregation (warp per edge)
    edge_agg<<<(E * 32 + 255) / 256, 256>>>(ei, E);
    // 7) bias + residual + layernorm
    ln_kernel<<<n, 256>>>(x, bias, ln_g, ln_b, n);
    // 8) FFN
    gemm64<true,  true><<<gg, 256>>>(hn,  W1, b1, hid, n);
    gemm64<false, true><<<gg, 256>>>(hid, W2, b2, (float*)d_out, n);
}

// round 3
// speedup vs baseline: 2.0689x; 2.0689x over previous
#include <cuda_runtime.h>
#include <cuda_bf16.h>

// ---------------- problem constants ----------------
#define DD 256
#define HH 8
#define HDD 32
#define N_MAX 50048
#define E_MAX 800000
#define NEG_SLOPE 0.2f

// ---------------- device scratch ----------------
__device__ float g_xp  [N_MAX * DD];   // x @ W
__device__ float g_asrc[N_MAX * HH];
__device__ float g_adst[N_MAX * HH];
__device__ float g_hn  [N_MAX * DD];   // post-layernorm
__device__ float g_hid [N_MAX * DD];   // FFN hidden
__device__ int   g_deg [N_MAX];        // in-degree
__device__ int   g_off [N_MAX];        // exclusive prefix (CSR offsets)
__device__ int   g_cur [N_MAX];        // fill cursor
__device__ int   g_srcl[E_MAX];        // CSR: source node per incoming edge

__device__ __forceinline__ float leaky(float v) {
    return v > 0.f ? v : NEG_SLOPE * v;
}

// ---------------- tiled fp32 GEMM: C[M,256] = A[M,256] @ B[256,256] ----------------
template <bool RELU, bool BIAS>
__global__ void gemm64(const float* __restrict__ A, const float* __restrict__ B,
                       const float* __restrict__ bias, float* __restrict__ C, int M) {
    __shared__ float As[64][33];
    __shared__ float Bs[32][65];
    const int tid  = threadIdx.x;              // 256 threads
    const int brow = blockIdx.x * 64;
    const int bcol = blockIdx.y * 64;
    const int tr   = tid >> 4;
    const int tc   = tid & 15;
    float acc[4][4] = {};

    for (int k0 = 0; k0 < 256; k0 += 32) {
#pragma unroll
        for (int t = 0; t < 8; t++) {
            int i = tid + t * 256;
            int r = i >> 5, c = i & 31;
            int gr = brow + r;
            As[r][c] = (gr < M) ? A[gr * 256 + k0 + c] : 0.f;
        }
#pragma unroll
        for (int t = 0; t < 8; t++) {
            int i = tid + t * 256;
            int r = i >> 6, c = i & 63;
            Bs[r][c] = B[(k0 + r) * 256 + bcol + c];
        }
        __syncthreads();
#pragma unroll
        for (int kk = 0; kk < 32; kk++) {
            float a[4], b[4];
#pragma unroll
            for (int i = 0; i < 4; i++) a[i] = As[tr * 4 + i][kk];
#pragma unroll
            for (int j = 0; j < 4; j++) b[j] = Bs[kk][tc * 4 + j];
#pragma unroll
            for (int i = 0; i < 4; i++)
#pragma unroll
                for (int j = 0; j < 4; j++)
                    acc[i][j] = fmaf(a[i], b[j], acc[i][j]);
        }
        __syncthreads();
    }
#pragma unroll
    for (int i = 0; i < 4; i++) {
        int gr = brow + tr * 4 + i;
        if (gr >= M) continue;
#pragma unroll
        for (int j = 0; j < 4; j++) {
            int gc = bcol + tc * 4 + j;
            float v = acc[i][j];
            if (BIAS) v += bias[gc];
            if (RELU) v = fmaxf(v, 0.f);
            C[gr * 256 + gc] = v;
        }
    }
}

// ---------------- per-node attention logits ----------------
__global__ void node_att(const float* __restrict__ att_src,
                         const float* __restrict__ att_dst, int n) {
    int i = blockIdx.x * blockDim.x + threadIdx.x;
    if (i >= n) return;
    const float* xp = g_xp + i * 256;
#pragma unroll
    for (int h = 0; h < HH; h++) {
        float s = 0.f, d = 0.f;
#pragma unroll
        for (int k = 0; k < HDD; k++) {
            float v = xp[h * HDD + k];
            s = fmaf(v, att_src[h * HDD + k], s);
            d = fmaf(v, att_dst[h * HDD + k], d);
        }
        g_asrc[i * HH + h] = s;
        g_adst[i * HH + h] = d;
    }
}

// ---------------- CSR build: degree count ----------------
__global__ void deg_count(const int* __restrict__ ei, int E) {
    int e = blockIdx.x * blockDim.x + threadIdx.x;
    if (e >= E) return;
    atomicAdd(&g_deg[ei[E + e]], 1);
}

// ---------------- CSR build: single-block exclusive scan over degrees ----------------
__global__ void scan_deg(int n) {
    __shared__ int wsum[32];
    __shared__ int s_carry;
    int tid = threadIdx.x, lane = tid & 31, wid = tid >> 5;
    if (tid == 0) s_carry = 0;
    __syncthreads();
    for (int base = 0; base < n; base += 1024) {
        int i = base + tid;
        int v = (i < n) ? g_deg[i] : 0;
        int x = v;
#pragma unroll
        for (int o = 1; o < 32; o <<= 1) {
            int t = __shfl_up_sync(0xffffffffu, x, o);
            if (lane >= o) x += t;
        }
        if (lane == 31) wsum[wid] = x;
        __syncthreads();
        if (wid == 0) {
            int w = wsum[lane];
#pragma unroll
            for (int o = 1; o < 32; o <<= 1) {
                int t = __shfl_up_sync(0xffffffffu, w, o);
                if (lane >= o) w += t;
            }
            wsum[lane] = w;
        }
        __syncthreads();
        int excl = s_carry + (wid ? wsum[wid - 1] : 0) + x - v;
        if (i < n) { g_off[i] = excl; g_cur[i] = excl; }
        __syncthreads();
        if (tid == 0) s_carry += wsum[31];
        __syncthreads();
    }
}

// ---------------- CSR build: fill source lists ----------------
__global__ void csr_fill(const int* __restrict__ ei, int E) {
    int e = blockIdx.x * blockDim.x + threadIdx.x;
    if (e >= E) return;
    int s = ei[e];
    int d = ei[E + e];
    int pos = atomicAdd(&g_cur[d], 1);
    g_srcl[pos] = s;
}

// ---------------- fused gather: softmax + aggregate + bias + residual + LN ----------------
// warp per destination node; warp holds full 256-channel row (8 floats/lane)
__global__ void gat_gather(const float* __restrict__ x,
                           const float* __restrict__ bias,
                           const float* __restrict__ gamma,
                           const float* __restrict__ beta, int n) {
    int warp = (blockIdx.x * blockDim.x + threadIdx.x) >> 5;
    int lane = threadIdx.x & 31;
    if (warp >= n) return;
    const int i  = warp;
    const int h0 = lane >> 3;        // head of channels [lane*4, lane*4+4)
    const int h1 = 4 + h0;           // head of channels [128+lane*4, ...)

    float4 acc0 = {0.f, 0.f, 0.f, 0.f};
    float4 acc1 = {0.f, 0.f, 0.f, 0.f};
    float  den  = 0.f;               // lanes 0..7 hold denom for head == lane
    float  adst = (lane < 8) ? g_adst[i * 8 + lane] : 0.f;

    const int start = g_off[i];
    const int deg   = g_deg[i];

    for (int e = 0; e < deg; e++) {
        int s = g_srcl[start + e];
        float ex = 0.f;
        if (lane < 8) {
            float v = leaky(g_asrc[s * 8 + lane] + adst);
            ex = __expf(v);          // no max-shift needed: |logit| small
            den += ex;
        }
        float e0 = __shfl_sync(0xffffffffu, ex, h0);
        float e1 = __shfl_sync(0xffffffffu, ex, h1);
        const float4* xs = (const float4*)(g_xp + s * 256);
        float4 v0 = xs[lane];
        float4 v1 = xs[32 + lane];
        acc0.x = fmaf(e0, v0.x, acc0.x); acc0.y = fmaf(e0, v0.y, acc0.y);
        acc0.z = fmaf(e0, v0.z, acc0.z); acc0.w = fmaf(e0, v0.w, acc0.w);
        acc1.x = fmaf(e1, v1.x, acc1.x); acc1.y = fmaf(e1, v1.y, acc1.y);
        acc1.z = fmaf(e1, v1.z, acc1.z); acc1.w = fmaf(e1, v1.w, acc1.w);
    }

    // self loop
    {
        float ex = 0.f;
        if (lane < 8) {
            float v = leaky(g_asrc[i * 8 + lane] + adst);
            ex = __expf(v);
            den += ex;
        }
        float e0 = __shfl_sync(0xffffffffu, ex, h0);
        float e1 = __shfl_sync(0xffffffffu, ex, h1);
        const float4* xs = (const float4*)(g_xp + i * 256);
        float4 v0 = xs[lane];
        float4 v1 = xs[32 + lane];
        acc0.x = fmaf(e0, v0.x, acc0.x); acc0.y = fmaf(e0, v0.y, acc0.y);
        acc0.z = fmaf(e0, v0.z, acc0.z); acc0.w = fmaf(e0, v0.w, acc0.w);
        acc1.x = fmaf(e1, v1.x, acc1.x); acc1.y = fmaf(e1, v1.y, acc1.y);
        acc1.z = fmaf(e1, v1.z, acc1.z); acc1.w = fmaf(e1, v1.w, acc1.w);
    }

    float inv0 = 1.f / (__shfl_sync(0xffffffffu, den, h0) + 1e-16f);
    float inv1 = 1.f / (__shfl_sync(0xffffffffu, den, h1) + 1e-16f);

    // bias + residual
    const float4* xr = (const float4*)(x + i * 256);
    const float4* bi = (const float4*)bias;
    float4 xv0 = xr[lane],      xv1 = xr[32 + lane];
    float4 b0  = bi[lane],      b1  = bi[32 + lane];
    float r[8];
    r[0] = fmaf(acc0.x, inv0, b0.x) + xv0.x;
    r[1] = fmaf(acc0.y, inv0, b0.y) + xv0.y;
    r[2] = fmaf(acc0.z, inv0, b0.z) + xv0.z;
    r[3] = fmaf(acc0.w, inv0, b0.w) + xv0.w;
    r[4] = fmaf(acc1.x, inv1, b1.x) + xv1.x;
    r[5] = fmaf(acc1.y, inv1, b1.y) + xv1.y;
    r[6] = fmaf(acc1.z, inv1, b1.z) + xv1.z;
    r[7] = fmaf(acc1.w, inv1, b1.w) + xv1.w;

    // warp LayerNorm over 256 channels
    float s = r[0] + r[1] + r[2] + r[3] + r[4] + r[5] + r[6] + r[7];
#pragma unroll
    for (int o = 16; o; o >>= 1) s += __shfl_xor_sync(0xffffffffu, s, o);
    float mu = s * (1.0f / 256.0f);
    float c[8], v2 = 0.f;
#pragma unroll
    for (int k = 0; k < 8; k++) { c[k] = r[k] - mu; v2 = fmaf(c[k], c[k], v2); }
#pragma unroll
    for (int o = 16; o; o >>= 1) v2 += __shfl_xor_sync(0xffffffffu, v2, o);
    float rstd = rsqrtf(v2 * (1.0f / 256.0f) + 1e-5f);

    const float4* gp = (const float4*)gamma;
    const float4* bp = (const float4*)beta;
    float4 g0 = gp[lane], g1 = gp[32 + lane];
    float4 p0 = bp[lane], p1 = bp[32 + lane];
    float4 o0, o1;
    o0.x = fmaf(c[0] * rstd, g0.x, p0.x);
    o0.y = fmaf(c[1] * rstd, g0.y, p0.y);
    o0.z = fmaf(c[2] * rstd, g0.z, p0.z);
    o0.w = fmaf(c[3] * rstd, g0.w, p0.w);
    o1.x = fmaf(c[4] * rstd, g1.x, p1.x);
    o1.y = fmaf(c[5] * rstd, g1.y, p1.y);
    o1.z = fmaf(c[6] * rstd, g1.z, p1.z);
    o1.w = fmaf(c[7] * rstd, g1.w, p1.w);
    float4* out = (float4*)(g_hn + i * 256);
    out[lane]      = o0;
    out[32 + lane] = o1;
}

// ---------------- launch ----------------
extern "C" void kernel_launch(void* const* d_in, const int* in_sizes, int n_in,
                              void* d_out, int out_size) {
    const float* x       = (const float*)d_in[0];
    const int*   ei      = (const int*)d_in[1];   // int32 (JAX x64 disabled)
    const float* W       = (const float*)d_in[3];
    const float* att_src = (const float*)d_in[4];
    const float* att_dst = (const float*)d_in[5];
    const float* bias    = (const float*)d_in[6];
    const float* ln_g    = (const float*)d_in[7];
    const float* ln_b    = (const float*)d_in[8];
    const float* W1      = (const float*)d_in[9];
    const float* b1      = (const float*)d_in[10];
    const float* W2      = (const float*)d_in[11];
    const float* b2      = (const float*)d_in[12];

    const int n = in_sizes[0] / DD;       // 50000
    const int E = in_sizes[1] / 2;        // 800000

    float *xp, *hn, *hid;
    int   *deg;
    cudaGetSymbolAddress((void**)&xp,  g_xp);
    cudaGetSymbolAddress((void**)&hn,  g_hn);
    cudaGetSymbolAddress((void**)&hid, g_hid);
    cudaGetSymbolAddress((void**)&deg, g_deg);

    dim3 gg((n + 63) / 64, 4);

    cudaMemsetAsync(deg, 0, n * sizeof(int), 0);
    // 1) xp = x @ W
    gemm64<false, false><<<gg, 256>>>(x, W, nullptr, xp, n);
    // 2) attention logits
    node_att<<<(n + 255) / 256, 256>>>(att_src, att_dst, n);
    // 3) CSR build
    deg_count<<<(E + 255) / 256, 256>>>(ei, E);
    scan_deg<<<1, 1024>>>(n);
    csr_fill<<<(E + 255) / 256, 256>>>(ei, E);
    // 4) fused softmax + gather + bias + residual + LN
    gat_gather<<<(n * 32 + 255) / 256, 256>>>(x, bias, ln_g, ln_b, n);
    // 5) FFN
    gemm64<true,  true><<<gg, 256>>>(hn,  W1, b1, hid, n);
    gemm64<false, true><<<gg, 256>>>(hid, W2, b2, (float*)d_out, n);
}

// round 4
// speedup vs baseline: 3.8606x; 1.8660x over previous
#include <cuda_runtime.h>
#include <cuda_bf16.h>

// ---------------- problem constants ----------------
#define DD 256
#define HH 8
#define HDD 32
#define N_MAX 50048
#define E_MAX 800000
#define NEG_SLOPE 0.2f

// ---------------- device scratch ----------------
__device__ __align__(256) float g_xp  [N_MAX * DD];   // x @ W
__device__ __align__(256) float g_asrc[N_MAX * HH];
__device__ __align__(256) float g_adst[N_MAX * HH];
__device__ __align__(256) float g_hn  [N_MAX * DD];   // post-layernorm
__device__ __align__(256) float g_hid [N_MAX * DD];   // FFN hidden
__device__ __align__(256) int   g_deg [N_MAX];        // in-degree
__device__ __align__(256) int   g_off [N_MAX];        // exclusive prefix
__device__ __align__(256) int   g_cur [N_MAX];        // fill cursor
__device__ __align__(256) int   g_srcl[E_MAX];        // CSR: source per incoming edge

__device__ __forceinline__ float leaky(float v) {
    return v > 0.f ? v : NEG_SLOPE * v;
}

// ---------------- tf32 helpers ----------------
__device__ __forceinline__ void split_tf32(float a, unsigned& hi, unsigned& lo) {
    unsigned h;
    asm("cvt.rna.tf32.f32 %0, %1;" : "=r"(h) : "f"(a));
    hi = h;
    // lo passed raw: HMMA.TF32 truncates low mantissa bits; residual error ~2^-22
    lo = __float_as_uint(a - __uint_as_float(h));
}

__device__ __forceinline__ void mma8(float* c, const unsigned* a, const unsigned* b) {
    asm("mma.sync.aligned.m16n8k8.row.col.f32.tf32.tf32.f32 "
        "{%0,%1,%2,%3}, {%4,%5,%6,%7}, {%8,%9}, {%0,%1,%2,%3};"
        : "+f"(c[0]), "+f"(c[1]), "+f"(c[2]), "+f"(c[3])
        : "r"(a[0]), "r"(a[1]), "r"(a[2]), "r"(a[3]), "r"(b[0]), "r"(b[1]));
}

// ---------------- tensor-core GEMM (3xTF32): C[M,256] = A[M,256] @ B[256,256] ----------------
// block: 256 threads = 8 warps (4 x 2), tile 128 x 64; warp tile 32 x 32
template <bool RELU, bool BIAS>
__global__ __launch_bounds__(256)
void gemm_tc(const float* __restrict__ A, const float* __restrict__ B,
             const float* __restrict__ bias, float* __restrict__ C, int M) {
    __shared__ float As[128][36];   // pad 36: frag loads conflict-free, float4-store aligned
    __shared__ float Bs[32][68];
    const int tid  = threadIdx.x;
    const int lane = tid & 31;
    const int warp = tid >> 5;
    const int wm   = warp & 3;       // 0..3 (m), 32 rows each
    const int wn   = warp >> 2;      // 0..1 (n), 32 cols each
    const int brow = blockIdx.x * 128;
    const int bcol = blockIdx.y * 64;
    const int q    = lane >> 2;      // 0..7
    const int tq   = lane & 3;       // 0..3

    float acc[2][4][4];
#pragma unroll
    for (int mt = 0; mt < 2; mt++)
#pragma unroll
        for (int nt = 0; nt < 4; nt++)
#pragma unroll
            for (int k = 0; k < 4; k++) acc[mt][nt][k] = 0.f;

    for (int k0 = 0; k0 < 256; k0 += 32) {
        // load A tile 128x32
        {
            int r0 = tid >> 3;
            int c4 = (tid & 7) * 4;
#pragma unroll
            for (int j = 0; j < 4; j++) {
                int r  = r0 + 32 * j;
                int gr = brow + r;
                float4 v = make_float4(0.f, 0.f, 0.f, 0.f);
                if (gr < M) v = *(const float4*)(A + gr * 256 + k0 + c4);
                *(float4*)&As[r][c4] = v;
            }
        }
        // load B tile 32x64
        {
#pragma unroll
            for (int j = 0; j < 2; j++) {
                int f  = tid + 256 * j;
                int r  = f >> 4;
                int cg = (f & 15) * 4;
                *(float4*)&Bs[r][cg] = *(const float4*)(B + (k0 + r) * 256 + bcol + cg);
            }
        }
        __syncthreads();

#pragma unroll
        for (int kk = 0; kk < 4; kk++) {
            const int kb = kk * 8;
            unsigned bh[4][2], bl[4][2];
#pragma unroll
            for (int nt = 0; nt < 4; nt++) {
                int col = wn * 32 + nt * 8 + q;
                int row = kb + tq;
                split_tf32(Bs[row][col],     bh[nt][0], bl[nt][0]);
                split_tf32(Bs[row + 4][col], bh[nt][1], bl[nt][1]);
            }
            unsigned ah[2][4], al[2][4];
#pragma unroll
            for (int mt = 0; mt < 2; mt++) {
                int r0 = wm * 32 + mt * 16 + q;
                int c  = kb + tq;
                split_tf32(As[r0][c],         ah[mt][0], al[mt][0]);
                split_tf32(As[r0 + 8][c],     ah[mt][1], al[mt][1]);
                split_tf32(As[r0][c + 4],     ah[mt][2], al[mt][2]);
                split_tf32(As[r0 + 8][c + 4], ah[mt][3], al[mt][3]);
            }
#pragma unroll
            for (int mt = 0; mt < 2; mt++)
#pragma unroll
                for (int nt = 0; nt < 4; nt++) {
                    mma8(acc[mt][nt], al[mt], bh[nt]);
                    mma8(acc[mt][nt], ah[mt], bl[nt]);
                    mma8(acc[mt][nt], ah[mt], bh[nt]);
                }
        }
        __syncthreads();
    }

    // epilogue
#pragma unroll
    for (int mt = 0; mt < 2; mt++) {
        int gr0 = brow + wm * 32 + mt * 16 + q;
#pragma unroll
        for (int nt = 0; nt < 4; nt++) {
            int gc = bcol + wn * 32 + nt * 8 + 2 * tq;
            float bx = 0.f, by = 0.f;
            if (BIAS) { bx = bias[gc]; by = bias[gc + 1]; }
            float2 v0 = make_float2(acc[mt][nt][0] + bx, acc[mt][nt][1] + by);
            float2 v1 = make_float2(acc[mt][nt][2] + bx, acc[mt][nt][3] + by);
            if (RELU) {
                v0.x = fmaxf(v0.x, 0.f); v0.y = fmaxf(v0.y, 0.f);
                v1.x = fmaxf(v1.x, 0.f); v1.y = fmaxf(v1.y, 0.f);
            }
            if (gr0 < M)     *(float2*)(C + gr0 * 256 + gc)       = v0;
            if (gr0 + 8 < M) *(float2*)(C + (gr0 + 8) * 256 + gc) = v1;
        }
    }
}

// ---------------- per-node attention logits ----------------
__global__ void node_att(const float* __restrict__ att_src,
                         const float* __restrict__ att_dst, int n) {
    int i = blockIdx.x * blockDim.x + threadIdx.x;
    if (i >= n) return;
    const float* xp = g_xp + i * 256;
#pragma unroll
    for (int h = 0; h < HH; h++) {
        float s = 0.f, d = 0.f;
#pragma unroll
        for (int k = 0; k < HDD; k++) {
            float v = xp[h * HDD + k];
            s = fmaf(v, att_src[h * HDD + k], s);
            d = fmaf(v, att_dst[h * HDD + k], d);
        }
        g_asrc[i * HH + h] = s;
        g_adst[i * HH + h] = d;
    }
}

// ---------------- CSR build: degree count ----------------
__global__ void deg_count(const int* __restrict__ ei, int E) {
    int e = blockIdx.x * blockDim.x + threadIdx.x;
    if (e >= E) return;
    atomicAdd(&g_deg[ei[E + e]], 1);
}

// ---------------- CSR build: single-block exclusive scan (int4 vectorized) ----------------
__global__ void scan_deg(int n) {
    __shared__ int wsum[32];
    __shared__ int s_carry;
    int tid = threadIdx.x, lane = tid & 31, wid = tid >> 5;
    if (tid == 0) s_carry = 0;
    __syncthreads();
    int n4 = (n + 3) >> 2;
    for (int base = 0; base < n4; base += 1024) {
        int f = base + tid;
        int4 v = make_int4(0, 0, 0, 0);
        if (f < n4) {
            if (f * 4 + 3 < n) v = ((const int4*)g_deg)[f];
            else {
                if (f * 4 + 0 < n) v.x = g_deg[f * 4 + 0];
                if (f * 4 + 1 < n) v.y = g_deg[f * 4 + 1];
                if (f * 4 + 2 < n) v.z = g_deg[f * 4 + 2];
            }
        }
        int tsum = v.x + v.y + v.z + v.w;
        int x = tsum;
#pragma unroll
        for (int o = 1; o < 32; o <<= 1) {
            int t = __shfl_up_sync(0xffffffffu, x, o);
            if (lane >= o) x += t;
        }
        if (lane == 31) wsum[wid] = x;
        __syncthreads();
        if (wid == 0) {
            int w = wsum[lane];
#pragma unroll
            for (int o = 1; o < 32; o <<= 1) {
                int t = __shfl_up_sync(0xffffffffu, w, o);
                if (lane >= o) w += t;
            }
            wsum[lane] = w;
        }
        __syncthreads();
        int excl = s_carry + (wid ? wsum[wid - 1] : 0) + x - tsum;
        int4 o4;
        o4.x = excl;
        o4.y = o4.x + v.x;
        o4.z = o4.y + v.y;
        o4.w = o4.z + v.z;
        if (f < n4) {
            if (f * 4 + 3 < n) { ((int4*)g_off)[f] = o4; ((int4*)g_cur)[f] = o4; }
            else {
                if (f * 4 + 0 < n) { g_off[f * 4 + 0] = o4.x; g_cur[f * 4 + 0] = o4.x; }
                if (f * 4 + 1 < n) { g_off[f * 4 + 1] = o4.y; g_cur[f * 4 + 1] = o4.y; }
                if (f * 4 + 2 < n) { g_off[f * 4 + 2] = o4.z; g_cur[f * 4 + 2] = o4.z; }
            }
        }
        __syncthreads();
        if (tid == 0) s_carry += wsum[31];
        __syncthreads();
    }
}

// ---------------- CSR build: fill source lists ----------------
__global__ void csr_fill(const int* __restrict__ ei, int E) {
    int e = blockIdx.x * blockDim.x + threadIdx.x;
    if (e >= E) return;
    int s = ei[e];
    int d = ei[E + e];
    int pos = atomicAdd(&g_cur[d], 1);
    g_srcl[pos] = s;
}

// ---------------- fused gather: softmax + aggregate + bias + residual + LN ----------------
__global__ void gat_gather(const float* __restrict__ x,
                           const float* __restrict__ bias,
                           const float* __restrict__ gamma,
                           const float* __restrict__ beta, int n) {
    int warp = (blockIdx.x * blockDim.x + threadIdx.x) >> 5;
    int lane = threadIdx.x & 31;
    if (warp >= n) return;
    const int i  = warp;
    const int h0 = lane >> 3;
    const int h1 = 4 + h0;

    float4 acc0 = {0.f, 0.f, 0.f, 0.f};
    float4 acc1 = {0.f, 0.f, 0.f, 0.f};
    float  den  = 0.f;
    float  adst = (lane < 8) ? g_adst[i * 8 + lane] : 0.f;

    const int start = g_off[i];
    const int deg   = g_deg[i];

    for (int e = 0; e < deg; e++) {
        int s = g_srcl[start + e];
        float ex = 0.f;
        if (lane < 8) {
            float v = leaky(g_asrc[s * 8 + lane] + adst);
            ex = __expf(v);
            den += ex;
        }
        float e0 = __shfl_sync(0xffffffffu, ex, h0);
        float e1 = __shfl_sync(0xffffffffu, ex, h1);
        const float4* xs = (const float4*)(g_xp + s * 256);
        float4 v0 = xs[lane];
        float4 v1 = xs[32 + lane];
        acc0.x = fmaf(e0, v0.x, acc0.x); acc0.y = fmaf(e0, v0.y, acc0.y);
        acc0.z = fmaf(e0, v0.z, acc0.z); acc0.w = fmaf(e0, v0.w, acc0.w);
        acc1.x = fmaf(e1, v1.x, acc1.x); acc1.y = fmaf(e1, v1.y, acc1.y);
        acc1.z = fmaf(e1, v1.z, acc1.z); acc1.w = fmaf(e1, v1.w, acc1.w);
    }

    // self loop
    {
        float ex = 0.f;
        if (lane < 8) {
            float v = leaky(g_asrc[i * 8 + lane] + adst);
            ex = __expf(v);
            den += ex;
        }
        float e0 = __shfl_sync(0xffffffffu, ex, h0);
        float e1 = __shfl_sync(0xffffffffu, ex, h1);
        const float4* xs = (const float4*)(g_xp + i * 256);
        float4 v0 = xs[lane];
        float4 v1 = xs[32 + lane];
        acc0.x = fmaf(e0, v0.x, acc0.x); acc0.y = fmaf(e0, v0.y, acc0.y);
        acc0.z = fmaf(e0, v0.z, acc0.z); acc0.w = fmaf(e0, v0.w, acc0.w);
        acc1.x = fmaf(e1, v1.x, acc1.x); acc1.y = fmaf(e1, v1.y, acc1.y);
        acc1.z = fmaf(e1, v1.z, acc1.z); acc1.w = fmaf(e1, v1.w, acc1.w);
    }

    float inv0 = 1.f / (__shfl_sync(0xffffffffu, den, h0) + 1e-16f);
    float inv1 = 1.f / (__shfl_sync(0xffffffffu, den, h1) + 1e-16f);

    const float4* xr = (const float4*)(x + i * 256);
    const float4* bi = (const float4*)bias;
    float4 xv0 = xr[lane], xv1 = xr[32 + lane];
    float4 b0  = bi[lane], b1  = bi[32 + lane];
    float r[8];
    r[0] = fmaf(acc0.x, inv0, b0.x) + xv0.x;
    r[1] = fmaf(acc0.y, inv0, b0.y) + xv0.y;
    r[2] = fmaf(acc0.z, inv0, b0.z) + xv0.z;
    r[3] = fmaf(acc0.w, inv0, b0.w) + xv0.w;
    r[4] = fmaf(acc1.x, inv1, b1.x) + xv1.x;
    r[5] = fmaf(acc1.y, inv1, b1.y) + xv1.y;
    r[6] = fmaf(acc1.z, inv1, b1.z) + xv1.z;
    r[7] = fmaf(acc1.w, inv1, b1.w) + xv1.w;

    float s = r[0] + r[1] + r[2] + r[3] + r[4] + r[5] + r[6] + r[7];
#pragma unroll
    for (int o = 16; o; o >>= 1) s += __shfl_xor_sync(0xffffffffu, s, o);
    float mu = s * (1.0f / 256.0f);
    float c[8], v2 = 0.f;
#pragma unroll
    for (int k = 0; k < 8; k++) { c[k] = r[k] - mu; v2 = fmaf(c[k], c[k], v2); }
#pragma unroll
    for (int o = 16; o; o >>= 1) v2 += __shfl_xor_sync(0xffffffffu, v2, o);
    float rstd = rsqrtf(v2 * (1.0f / 256.0f) + 1e-5f);

    const float4* gp = (const float4*)gamma;
    const float4* bp = (const float4*)beta;
    float4 g0 = gp[lane], g1 = gp[32 + lane];
    float4 p0 = bp[lane], p1 = bp[32 + lane];
    float4 o0, o1;
    o0.x = fmaf(c[0] * rstd, g0.x, p0.x);
    o0.y = fmaf(c[1] * rstd, g0.y, p0.y);
    o0.z = fmaf(c[2] * rstd, g0.z, p0.z);
    o0.w = fmaf(c[3] * rstd, g0.w, p0.w);
    o1.x = fmaf(c[4] * rstd, g1.x, p1.x);
    o1.y = fmaf(c[5] * rstd, g1.y, p1.y);
    o1.z = fmaf(c[6] * rstd, g1.z, p1.z);
    o1.w = fmaf(c[7] * rstd, g1.w, p1.w);
    float4* out = (float4*)(g_hn + i * 256);
    out[lane]      = o0;
    out[32 + lane] = o1;
}

// ---------------- launch ----------------
extern "C" void kernel_launch(void* const* d_in, const int* in_sizes, int n_in,
                              void* d_out, int out_size) {
    const float* x       = (const float*)d_in[0];
    const int*   ei      = (const int*)d_in[1];   // int32 (JAX x64 disabled)
    const float* W       = (const float*)d_in[3];
    const float* att_src = (const float*)d_in[4];
    const float* att_dst = (const float*)d_in[5];
    const float* bias    = (const float*)d_in[6];
    const float* ln_g    = (const float*)d_in[7];
    const float* ln_b    = (const float*)d_in[8];
    const float* W1      = (const float*)d_in[9];
    const float* b1      = (const float*)d_in[10];
    const float* W2      = (const float*)d_in[11];
    const float* b2      = (const float*)d_in[12];

    const int n = in_sizes[0] / DD;       // 50000
    const int E = in_sizes[1] / 2;        // 800000

    float *xp, *hn, *hid;
    int   *deg;
    cudaGetSymbolAddress((void**)&xp,  g_xp);
    cudaGetSymbolAddress((void**)&hn,  g_hn);
    cudaGetSymbolAddress((void**)&hid, g_hid);
    cudaGetSymbolAddress((void**)&deg, g_deg);

    dim3 gg((n + 127) / 128, 4);

    cudaMemsetAsync(deg, 0, n * sizeof(int), 0);
    // 1) xp = x @ W  (tensor cores, 3xTF32)
    gemm_tc<false, false><<<gg, 256>>>(x, W, nullptr, xp, n);
    // 2) attention logits
    node_att<<<(n + 255) / 256, 256>>>(att_src, att_dst, n);
    // 3) CSR build
    deg_count<<<(E + 255) / 256, 256>>>(ei, E);
    scan_deg<<<1, 1024>>>(n);
    csr_fill<<<(E + 255) / 256, 256>>>(ei, E);
    // 4) fused softmax + gather + bias + residual + LN
    gat_gather<<<(n * 32 + 255) / 256, 256>>>(x, bias, ln_g, ln_b, n);
    // 5) FFN
    gemm_tc<true,  true><<<gg, 256>>>(hn,  W1, b1, hid, n);
    gemm_tc<false, true><<<gg, 256>>>(hid, W2, b2, (float*)d_out, n);
}

// round 5
// speedup vs baseline: 4.0665x; 1.0533x over previous
#include <cuda_runtime.h>
#include <cuda_bf16.h>

// ---------------- problem constants ----------------
#define DD 256
#define HH 8
#define HDD 32
#define N_MAX 50048
#define E_MAX 800000
#define NEG_SLOPE 0.2f

// ---------------- device scratch ----------------
__device__ __align__(256) float g_xp  [N_MAX * DD];   // x @ W
__device__ __align__(256) float g_asrc[N_MAX * HH];
__device__ __align__(256) float g_adst[N_MAX * HH];
__device__ __align__(256) float g_hn  [N_MAX * DD];   // post-layernorm
__device__ __align__(256) float g_hid [N_MAX * DD];   // FFN hidden
__device__ __align__(256) int   g_deg [N_MAX];        // in-degree
__device__ __align__(256) int   g_off [N_MAX];        // exclusive prefix
__device__ __align__(256) int   g_cur [N_MAX];        // fill cursor
__device__ __align__(256) int   g_srcl[E_MAX];        // CSR: source per incoming edge
__device__ int g_bsum[64];                             // scan block sums

__device__ __forceinline__ float leaky(float v) {
    return v > 0.f ? v : NEG_SLOPE * v;
}

// ---------------- tf32 helpers ----------------
__device__ __forceinline__ void split_tf32(float a, unsigned& hi, unsigned& lo) {
    unsigned h;
    asm("cvt.rna.tf32.f32 %0, %1;" : "=r"(h) : "f"(a));
    hi = h;
    lo = __float_as_uint(a - __uint_as_float(h));
}

__device__ __forceinline__ void mma8(float* c, const unsigned* a, const unsigned* b) {
    asm("mma.sync.aligned.m16n8k8.row.col.f32.tf32.tf32.f32 "
        "{%0,%1,%2,%3}, {%4,%5,%6,%7}, {%8,%9}, {%0,%1,%2,%3};"
        : "+f"(c[0]), "+f"(c[1]), "+f"(c[2]), "+f"(c[3])
        : "r"(a[0]), "r"(a[1]), "r"(a[2]), "r"(a[3]), "r"(b[0]), "r"(b[1]));
}

// ---------------- tensor-core GEMM (3xTF32), register double-buffered ----------------
// block: 256 threads = 8 warps (4 x 2), tile 128 x 64; warp tile 32 x 32
template <bool RELU, bool BIAS>
__global__ __launch_bounds__(256)
void gemm_tc(const float* __restrict__ A, const float* __restrict__ B,
             const float* __restrict__ bias, float* __restrict__ C, int M) {
    __shared__ float As[128][36];
    __shared__ float Bs[32][68];
    const int tid  = threadIdx.x;
    const int lane = tid & 31;
    const int warp = tid >> 5;
    const int wm   = warp & 3;
    const int wn   = warp >> 2;
    const int brow = blockIdx.x * 128;
    const int bcol = blockIdx.y * 64;
    const int q    = lane >> 2;
    const int tq   = lane & 3;

    const int ar0 = tid >> 3;
    const int ac4 = (tid & 7) * 4;
    const int br  = tid >> 4;           // row within B tile for part 0
    const int bc4 = (tid & 15) * 4;

    float acc[2][4][4];
#pragma unroll
    for (int mt = 0; mt < 2; mt++)
#pragma unroll
        for (int nt = 0; nt < 4; nt++)
#pragma unroll
            for (int k = 0; k < 4; k++) acc[mt][nt][k] = 0.f;

    float4 pa[4], pb[2];

    // prologue: load tile k0=0
#pragma unroll
    for (int j = 0; j < 4; j++) {
        int gr = brow + ar0 + 32 * j;
        pa[j] = (gr < M) ? *(const float4*)(A + gr * 256 + ac4)
                         : make_float4(0.f, 0.f, 0.f, 0.f);
    }
    pb[0] = *(const float4*)(B + br * 256 + bcol + bc4);
    pb[1] = *(const float4*)(B + (16 + br) * 256 + bcol + bc4);
#pragma unroll
    for (int j = 0; j < 4; j++) *(float4*)&As[ar0 + 32 * j][ac4] = pa[j];
    *(float4*)&Bs[br][bc4]      = pb[0];
    *(float4*)&Bs[16 + br][bc4] = pb[1];
    __syncthreads();

    for (int k0 = 0; k0 < 8; k0++) {
        // prefetch next tile into registers
        if (k0 < 7) {
            int kb = (k0 + 1) * 32;
#pragma unroll
            for (int j = 0; j < 4; j++) {
                int gr = brow + ar0 + 32 * j;
                pa[j] = (gr < M) ? *(const float4*)(A + gr * 256 + kb + ac4)
                                 : make_float4(0.f, 0.f, 0.f, 0.f);
            }
            pb[0] = *(const float4*)(B + (kb + br) * 256 + bcol + bc4);
            pb[1] = *(const float4*)(B + (kb + 16 + br) * 256 + bcol + bc4);
        }

#pragma unroll
        for (int kk = 0; kk < 4; kk++) {
            const int kb = kk * 8;
            unsigned bh[4][2], bl[4][2];
#pragma unroll
            for (int nt = 0; nt < 4; nt++) {
                int col = wn * 32 + nt * 8 + q;
                int row = kb + tq;
                split_tf32(Bs[row][col],     bh[nt][0], bl[nt][0]);
                split_tf32(Bs[row + 4][col], bh[nt][1], bl[nt][1]);
            }
            unsigned ah[2][4], al[2][4];
#pragma unroll
            for (int mt = 0; mt < 2; mt++) {
                int r0 = wm * 32 + mt * 16 + q;
                int c  = kb + tq;
                split_tf32(As[r0][c],         ah[mt][0], al[mt][0]);
                split_tf32(As[r0 + 8][c],     ah[mt][1], al[mt][1]);
                split_tf32(As[r0][c + 4],     ah[mt][2], al[mt][2]);
                split_tf32(As[r0 + 8][c + 4], ah[mt][3], al[mt][3]);
            }
#pragma unroll
            for (int mt = 0; mt < 2; mt++)
#pragma unroll
                for (int nt = 0; nt < 4; nt++) {
                    mma8(acc[mt][nt], al[mt], bh[nt]);
                    mma8(acc[mt][nt], ah[mt], bl[nt]);
                    mma8(acc[mt][nt], ah[mt], bh[nt]);
                }
        }
        __syncthreads();
        if (k0 < 7) {
#pragma unroll
            for (int j = 0; j < 4; j++) *(float4*)&As[ar0 + 32 * j][ac4] = pa[j];
            *(float4*)&Bs[br][bc4]      = pb[0];
            *(float4*)&Bs[16 + br][bc4] = pb[1];
            __syncthreads();
        }
    }

    // epilogue
#pragma unroll
    for (int mt = 0; mt < 2; mt++) {
        int gr0 = brow + wm * 32 + mt * 16 + q;
#pragma unroll
        for (int nt = 0; nt < 4; nt++) {
            int gc = bcol + wn * 32 + nt * 8 + 2 * tq;
            float bx = 0.f, by = 0.f;
            if (BIAS) { bx = bias[gc]; by = bias[gc + 1]; }
            float2 v0 = make_float2(acc[mt][nt][0] + bx, acc[mt][nt][1] + by);
            float2 v1 = make_float2(acc[mt][nt][2] + bx, acc[mt][nt][3] + by);
            if (RELU) {
                v0.x = fmaxf(v0.x, 0.f); v0.y = fmaxf(v0.y, 0.f);
                v1.x = fmaxf(v1.x, 0.f); v1.y = fmaxf(v1.y, 0.f);
            }
            if (gr0 < M)     *(float2*)(C + gr0 * 256 + gc)       = v0;
            if (gr0 + 8 < M) *(float2*)(C + (gr0 + 8) * 256 + gc) = v1;
        }
    }
}

// ---------------- per-node attention logits (warp per node) ----------------
__global__ void node_att(const float* __restrict__ att_src,
                         const float* __restrict__ att_dst, int n) {
    int warp = (blockIdx.x * blockDim.x + threadIdx.x) >> 5;
    int lane = threadIdx.x & 31;
    if (warp >= n) return;
    const int i = warp;
    // lane handles channels [lane*8, lane*8+8) -> head h = lane>>2
    const float4* xp = (const float4*)(g_xp + i * 256);
    float4 v0 = xp[lane * 2];
    float4 v1 = xp[lane * 2 + 1];
    const float4* as4 = (const float4*)att_src;
    const float4* ad4 = (const float4*)att_dst;
    float4 s0 = as4[lane * 2], s1 = as4[lane * 2 + 1];
    float4 d0 = ad4[lane * 2], d1 = ad4[lane * 2 + 1];
    float s = v0.x * s0.x + v0.y * s0.y + v0.z * s0.z + v0.w * s0.w
            + v1.x * s1.x + v1.y * s1.y + v1.z * s1.z + v1.w * s1.w;
    float d = v0.x * d0.x + v0.y * d0.y + v0.z * d0.z + v0.w * d0.w
            + v1.x * d1.x + v1.y * d1.y + v1.z * d1.z + v1.w * d1.w;
    // reduce over 4 lanes of same head
    s += __shfl_xor_sync(0xffffffffu, s, 1);
    s += __shfl_xor_sync(0xffffffffu, s, 2);
    d += __shfl_xor_sync(0xffffffffu, d, 1);
    d += __shfl_xor_sync(0xffffffffu, d, 2);
    if ((lane & 3) == 0) {
        int h = lane >> 2;
        g_asrc[i * 8 + h] = s;
        g_adst[i * 8 + h] = d;
    }
}

// ---------------- CSR build: degree count ----------------
__global__ void deg_count(const int* __restrict__ ei, int E) {
    int e = blockIdx.x * blockDim.x + threadIdx.x;
    if (e >= E) return;
    atomicAdd(&g_deg[ei[E + e]], 1);
}

// ---------------- multi-block scan ----------------
__global__ void scan_part(int n) {
    __shared__ int wsum[32];
    int tid = threadIdx.x, lane = tid & 31, wid = tid >> 5;
    int n4 = (n + 3) >> 2;
    int f = blockIdx.x * 1024 + tid;
    int4 v = make_int4(0, 0, 0, 0);
    if (f < n4) {
        if (f * 4 + 3 < n) v = ((const int4*)g_deg)[f];
        else {
            if (f * 4 + 0 < n) v.x = g_deg[f * 4 + 0];
            if (f * 4 + 1 < n) v.y = g_deg[f * 4 + 1];
            if (f * 4 + 2 < n) v.z = g_deg[f * 4 + 2];
        }
    }
    int tsum = v.x + v.y + v.z + v.w;
    int x = tsum;
#pragma unroll
    for (int o = 1; o < 32; o <<= 1) {
        int t = __shfl_up_sync(0xffffffffu, x, o);
        if (lane >= o) x += t;
    }
    if (lane == 31) wsum[wid] = x;
    __syncthreads();
    if (wid == 0) {
        int w = wsum[lane];
#pragma unroll
        for (int o = 1; o < 32; o <<= 1) {
            int t = __shfl_up_sync(0xffffffffu, w, o);
            if (lane >= o) w += t;
        }
        wsum[lane] = w;
    }
    __syncthreads();
    int excl = (wid ? wsum[wid - 1] : 0) + x - tsum;
    int4 o4;
    o4.x = excl;
    o4.y = o4.x + v.x;
    o4.z = o4.y + v.y;
    o4.w = o4.z + v.z;
    if (f < n4) {
        if (f * 4 + 3 < n) ((int4*)g_off)[f] = o4;
        else {
            if (f * 4 + 0 < n) g_off[f * 4 + 0] = o4.x;
            if (f * 4 + 1 < n) g_off[f * 4 + 1] = o4.y;
            if (f * 4 + 2 < n) g_off[f * 4 + 2] = o4.z;
        }
    }
    if (tid == 0) g_bsum[blockIdx.x] = wsum[31];
}

__global__ void scan_top(int nb) {
    int lane = threadIdx.x;
    int v = (lane < nb) ? g_bsum[lane] : 0;
    int x = v;
#pragma unroll
    for (int o = 1; o < 32; o <<= 1) {
        int t = __shfl_up_sync(0xffffffffu, x, o);
        if (lane >= o) x += t;
    }
    if (lane < nb) g_bsum[lane] = x - v;   // exclusive
}

__global__ void scan_add(int n) {
    int n4 = (n + 3) >> 2;
    int f = blockIdx.x * 1024 + threadIdx.x;
    if (f >= n4) return;
    int add = g_bsum[blockIdx.x];
    if (f * 4 + 3 < n) {
        int4 o = ((const int4*)g_off)[f];
        o.x += add; o.y += add; o.z += add; o.w += add;
        ((int4*)g_off)[f] = o;
        ((int4*)g_cur)[f] = o;
    } else {
#pragma unroll
        for (int j = 0; j < 3; j++)
            if (f * 4 + j < n) {
                int o = g_off[f * 4 + j] + add;
                g_off[f * 4 + j] = o;
                g_cur[f * 4 + j] = o;
            }
    }
}

// ---------------- CSR build: fill source lists ----------------
__global__ void csr_fill(const int* __restrict__ ei, int E) {
    int e = blockIdx.x * blockDim.x + threadIdx.x;
    if (e >= E) return;
    int s = ei[e];
    int d = ei[E + e];
    int pos = atomicAdd(&g_cur[d], 1);
    g_srcl[pos] = s;
}

// ---------------- fused gather: softmax + aggregate + bias + residual + LN ----------------
__global__ void gat_gather(const float* __restrict__ x,
                           const float* __restrict__ bias,
                           const float* __restrict__ gamma,
                           const float* __restrict__ beta, int n) {
    int warp = (blockIdx.x * blockDim.x + threadIdx.x) >> 5;
    int lane = threadIdx.x & 31;
    if (warp >= n) return;
    const int i  = warp;
    const int h0 = lane >> 3;
    const int h1 = 4 + h0;

    float4 acc0 = {0.f, 0.f, 0.f, 0.f};
    float4 acc1 = {0.f, 0.f, 0.f, 0.f};
    float  den  = 0.f;
    float  adst = (lane < 8) ? g_adst[i * 8 + lane] : 0.f;

    const int start = g_off[i];
    const int deg   = g_deg[i];

    int e = 0;
    for (; e + 2 <= deg; e += 2) {
        int s0 = g_srcl[start + e];
        int s1 = g_srcl[start + e + 1];
        float ex0 = 0.f, ex1 = 0.f;
        if (lane < 8) {
            ex0 = __expf(leaky(g_asrc[s0 * 8 + lane] + adst));
            ex1 = __expf(leaky(g_asrc[s1 * 8 + lane] + adst));
            den += ex0 + ex1;
        }
        float a00 = __shfl_sync(0xffffffffu, ex0, h0);
        float a01 = __shfl_sync(0xffffffffu, ex0, h1);
        float a10 = __shfl_sync(0xffffffffu, ex1, h0);
        float a11 = __shfl_sync(0xffffffffu, ex1, h1);
        const float4* xs0 = (const float4*)(g_xp + s0 * 256);
        const float4* xs1 = (const float4*)(g_xp + s1 * 256);
        float4 u0 = xs0[lane], u1 = xs0[32 + lane];
        float4 w0 = xs1[lane], w1 = xs1[32 + lane];
        acc0.x = fmaf(a00, u0.x, acc0.x); acc0.y = fmaf(a00, u0.y, acc0.y);
        acc0.z = fmaf(a00, u0.z, acc0.z); acc0.w = fmaf(a00, u0.w, acc0.w);
        acc1.x = fmaf(a01, u1.x, acc1.x); acc1.y = fmaf(a01, u1.y, acc1.y);
        acc1.z = fmaf(a01, u1.z, acc1.z); acc1.w = fmaf(a01, u1.w, acc1.w);
        acc0.x = fmaf(a10, w0.x, acc0.x); acc0.y = fmaf(a10, w0.y, acc0.y);
        acc0.z = fmaf(a10, w0.z, acc0.z); acc0.w = fmaf(a10, w0.w, acc0.w);
        acc1.x = fmaf(a11, w1.x, acc1.x); acc1.y = fmaf(a11, w1.y, acc1.y);
        acc1.z = fmaf(a11, w1.z, acc1.z); acc1.w = fmaf(a11, w1.w, acc1.w);
    }
    for (; e < deg; e++) {
        int s = g_srcl[start + e];
        float ex = 0.f;
        if (lane < 8) {
            ex = __expf(leaky(g_asrc[s * 8 + lane] + adst));
            den += ex;
        }
        float e0 = __shfl_sync(0xffffffffu, ex, h0);
        float e1 = __shfl_sync(0xffffffffu, ex, h1);
        const float4* xs = (const float4*)(g_xp + s * 256);
        float4 v0 = xs[lane], v1 = xs[32 + lane];
        acc0.x = fmaf(e0, v0.x, acc0.x); acc0.y = fmaf(e0, v0.y, acc0.y);
        acc0.z = fmaf(e0, v0.z, acc0.z); acc0.w = fmaf(e0, v0.w, acc0.w);
        acc1.x = fmaf(e1, v1.x, acc1.x); acc1.y = fmaf(e1, v1.y, acc1.y);
        acc1.z = fmaf(e1, v1.z, acc1.z); acc1.w = fmaf(e1, v1.w, acc1.w);
    }

    // self loop
    {
        float ex = 0.f;
        if (lane < 8) {
            ex = __expf(leaky(g_asrc[i * 8 + lane] + adst));
            den += ex;
        }
        float e0 = __shfl_sync(0xffffffffu, ex, h0);
        float e1 = __shfl_sync(0xffffffffu, ex, h1);
        const float4* xs = (const float4*)(g_xp + i * 256);
        float4 v0 = xs[lane], v1 = xs[32 + lane];
        acc0.x = fmaf(e0, v0.x, acc0.x); acc0.y = fmaf(e0, v0.y, acc0.y);
        acc0.z = fmaf(e0, v0.z, acc0.z); acc0.w = fmaf(e0, v0.w, acc0.w);
        acc1.x = fmaf(e1, v1.x, acc1.x); acc1.y = fmaf(e1, v1.y, acc1.y);
        acc1.z = fmaf(e1, v1.z, acc1.z); acc1.w = fmaf(e1, v1.w, acc1.w);
    }

    float inv0 = 1.f / (__shfl_sync(0xffffffffu, den, h0) + 1e-16f);
    float inv1 = 1.f / (__shfl_sync(0xffffffffu, den, h1) + 1e-16f);

    const float4* xr = (const float4*)(x + i * 256);
    const float4* bi = (const float4*)bias;
    float4 xv0 = xr[lane], xv1 = xr[32 + lane];
    float4 b0  = bi[lane], b1  = bi[32 + lane];
    float r[8];
    r[0] = fmaf(acc0.x, inv0, b0.x) + xv0.x;
    r[1] = fmaf(acc0.y, inv0, b0.y) + xv0.y;
    r[2] = fmaf(acc0.z, inv0, b0.z) + xv0.z;
    r[3] = fmaf(acc0.w, inv0, b0.w) + xv0.w;
    r[4] = fmaf(acc1.x, inv1, b1.x) + xv1.x;
    r[5] = fmaf(acc1.y, inv1, b1.y) + xv1.y;
    r[6] = fmaf(acc1.z, inv1, b1.z) + xv1.z;
    r[7] = fmaf(acc1.w, inv1, b1.w) + xv1.w;

    float s = r[0] + r[1] + r[2] + r[3] + r[4] + r[5] + r[6] + r[7];
#pragma unroll
    for (int o = 16; o; o >>= 1) s += __shfl_xor_sync(0xffffffffu, s, o);
    float mu = s * (1.0f / 256.0f);
    float c[8], v2 = 0.f;
#pragma unroll
    for (int k = 0; k < 8; k++) { c[k] = r[k] - mu; v2 = fmaf(c[k], c[k], v2); }
#pragma unroll
    for (int o = 16; o; o >>= 1) v2 += __shfl_xor_sync(0xffffffffu, v2, o);
    float rstd = rsqrtf(v2 * (1.0f / 256.0f) + 1e-5f);

    const float4* gp = (const float4*)gamma;
    const float4* bp = (const float4*)beta;
    float4 g0 = gp[lane], g1 = gp[32 + lane];
    float4 p0 = bp[lane], p1 = bp[32 + lane];
    float4 o0, o1;
    o0.x = fmaf(c[0] * rstd, g0.x, p0.x);
    o0.y = fmaf(c[1] * rstd, g0.y, p0.y);
    o0.z = fmaf(c[2] * rstd, g0.z, p0.z);
    o0.w = fmaf(c[3] * rstd, g0.w, p0.w);
    o1.x = fmaf(c[4] * rstd, g1.x, p1.x);
    o1.y = fmaf(c[5] * rstd, g1.y, p1.y);
    o1.z = fmaf(c[6] * rstd, g1.z, p1.z);
    o1.w = fmaf(c[7] * rstd, g1.w, p1.w);
    float4* out = (float4*)(g_hn + i * 256);
    out[lane]      = o0;
    out[32 + lane] = o1;
}

// ---------------- launch ----------------
extern "C" void kernel_launch(void* const* d_in, const int* in_sizes, int n_in,
                              void* d_out, int out_size) {
    const float* x       = (const float*)d_in[0];
    const int*   ei      = (const int*)d_in[1];   // int32 (JAX x64 disabled)
    const float* W       = (const float*)d_in[3];
    const float* att_src = (const float*)d_in[4];
    const float* att_dst = (const float*)d_in[5];
    const float* bias    = (const float*)d_in[6];
    const float* ln_g    = (const float*)d_in[7];
    const float* ln_b    = (const float*)d_in[8];
    const float* W1      = (const float*)d_in[9];
    const float* b1      = (const float*)d_in[10];
    const float* W2      = (const float*)d_in[11];
    const float* b2      = (const float*)d_in[12];

    const int n = in_sizes[0] / DD;       // 50000
    const int E = in_sizes[1] / 2;        // 800000

    float *xp, *hn, *hid;
    int   *deg;
    cudaGetSymbolAddress((void**)&xp,  g_xp);
    cudaGetSymbolAddress((void**)&hn,  g_hn);
    cudaGetSymbolAddress((void**)&hid, g_hid);
    cudaGetSymbolAddress((void**)&deg, g_deg);

    dim3 gg((n + 127) / 128, 4);
    const int n4 = (n + 3) >> 2;
    const int nscan = (n4 + 1023) / 1024;

    cudaMemsetAsync(deg, 0, n * sizeof(int), 0);
    // 1) xp = x @ W  (tensor cores, 3xTF32)
    gemm_tc<false, false><<<gg, 256>>>(x, W, nullptr, xp, n);
    // 2) attention logits (warp per node)
    node_att<<<(n * 32 + 255) / 256, 256>>>(att_src, att_dst, n);
    // 3) CSR build
    deg_count<<<(E + 255) / 256, 256>>>(ei, E);
    scan_part<<<nscan, 1024>>>(n);
    scan_top<<<1, 32>>>(nscan);
    scan_add<<<nscan, 1024>>>(n);
    csr_fill<<<(E + 255) / 256, 256>>>(ei, E);
    // 4) fused softmax + gather + bias + residual + LN
    gat_gather<<<(n * 32 + 255) / 256, 256>>>(x, bias, ln_g, ln_b, n);
    // 5) FFN
    gemm_tc<true,  true><<<gg, 256>>>(hn,  W1, b1, hid, n);
    gemm_tc<false, true><<<gg, 256>>>(hid, W2, b2, (float*)d_out, n);
}

// round 6
// speedup vs baseline: 4.1963x; 1.0319x over previous
#include <cuda_runtime.h>
#include <cuda_bf16.h>

// ---------------- problem constants ----------------
#define DD 256
#define HH 8
#define HDD 32
#define N_MAX 50048
#define E_MAX 800000
#define NEG_SLOPE 0.2f

// ---------------- device scratch ----------------
__device__ __align__(256) float g_xp  [N_MAX * DD];   // x @ W
__device__ __align__(256) float g_asrc[N_MAX * HH];
__device__ __align__(256) float g_adst[N_MAX * HH];
__device__ __align__(256) float g_hn  [N_MAX * DD];   // post-layernorm
__device__ __align__(256) float g_hid [N_MAX * DD];   // FFN hidden
__device__ __align__(256) int   g_deg [N_MAX];        // in-degree
__device__ __align__(256) int   g_off [N_MAX];        // exclusive prefix
__device__ __align__(256) int   g_cur [N_MAX];        // fill cursor
__device__ __align__(256) int   g_srcl[E_MAX];        // CSR: source per incoming edge
__device__ int g_bsum[64];                             // scan block sums

__device__ __forceinline__ float leaky(float v) {
    return v > 0.f ? v : NEG_SLOPE * v;
}

// ---------------- tf32 helpers ----------------
__device__ __forceinline__ void split_tf32(float a, unsigned& hi, unsigned& lo) {
    unsigned h;
    asm("cvt.rna.tf32.f32 %0, %1;" : "=r"(h) : "f"(a));
    hi = h;
    lo = __float_as_uint(a - __uint_as_float(h));
}

__device__ __forceinline__ void mma8(float* c, const unsigned* a, const unsigned* b) {
    asm("mma.sync.aligned.m16n8k8.row.col.f32.tf32.tf32.f32 "
        "{%0,%1,%2,%3}, {%4,%5,%6,%7}, {%8,%9}, {%0,%1,%2,%3};"
        : "+f"(c[0]), "+f"(c[1]), "+f"(c[2]), "+f"(c[3])
        : "r"(a[0]), "r"(a[1]), "r"(a[2]), "r"(a[3]), "r"(b[0]), "r"(b[1]));
}

// ---------------- tensor-core GEMM (3xTF32), register double-buffered ----------------
template <bool RELU, bool BIAS>
__global__ __launch_bounds__(256)
void gemm_tc(const float* __restrict__ A, const float* __restrict__ B,
             const float* __restrict__ bias, float* __restrict__ C, int M) {
    __shared__ float As[128][36];
    __shared__ float Bs[32][68];
    const int tid  = threadIdx.x;
    const int lane = tid & 31;
    const int warp = tid >> 5;
    const int wm   = warp & 3;
    const int wn   = warp >> 2;
    const int brow = blockIdx.x * 128;
    const int bcol = blockIdx.y * 64;
    const int q    = lane >> 2;
    const int tq   = lane & 3;

    const int ar0 = tid >> 3;
    const int ac4 = (tid & 7) * 4;
    const int br  = tid >> 4;
    const int bc4 = (tid & 15) * 4;

    float acc[2][4][4];
#pragma unroll
    for (int mt = 0; mt < 2; mt++)
#pragma unroll
        for (int nt = 0; nt < 4; nt++)
#pragma unroll
            for (int k = 0; k < 4; k++) acc[mt][nt][k] = 0.f;

    float4 pa[4], pb[2];

#pragma unroll
    for (int j = 0; j < 4; j++) {
        int gr = brow + ar0 + 32 * j;
        pa[j] = (gr < M) ? *(const float4*)(A + gr * 256 + ac4)
                         : make_float4(0.f, 0.f, 0.f, 0.f);
    }
    pb[0] = *(const float4*)(B + br * 256 + bcol + bc4);
    pb[1] = *(const float4*)(B + (16 + br) * 256 + bcol + bc4);
#pragma unroll
    for (int j = 0; j < 4; j++) *(float4*)&As[ar0 + 32 * j][ac4] = pa[j];
    *(float4*)&Bs[br][bc4]      = pb[0];
    *(float4*)&Bs[16 + br][bc4] = pb[1];
    __syncthreads();

    for (int k0 = 0; k0 < 8; k0++) {
        if (k0 < 7) {
            int kb = (k0 + 1) * 32;
#pragma unroll
            for (int j = 0; j < 4; j++) {
                int gr = brow + ar0 + 32 * j;
                pa[j] = (gr < M) ? *(const float4*)(A + gr * 256 + kb + ac4)
                                 : make_float4(0.f, 0.f, 0.f, 0.f);
            }
            pb[0] = *(const float4*)(B + (kb + br) * 256 + bcol + bc4);
            pb[1] = *(const float4*)(B + (kb + 16 + br) * 256 + bcol + bc4);
        }

#pragma unroll
        for (int kk = 0; kk < 4; kk++) {
            const int kb = kk * 8;
            unsigned bh[4][2], bl[4][2];
#pragma unroll
            for (int nt = 0; nt < 4; nt++) {
                int col = wn * 32 + nt * 8 + q;
                int row = kb + tq;
                split_tf32(Bs[row][col],     bh[nt][0], bl[nt][0]);
                split_tf32(Bs[row + 4][col], bh[nt][1], bl[nt][1]);
            }
            unsigned ah[2][4], al[2][4];
#pragma unroll
            for (int mt = 0; mt < 2; mt++) {
                int r0 = wm * 32 + mt * 16 + q;
                int c  = kb + tq;
                split_tf32(As[r0][c],         ah[mt][0], al[mt][0]);
                split_tf32(As[r0 + 8][c],     ah[mt][1], al[mt][1]);
                split_tf32(As[r0][c + 4],     ah[mt][2], al[mt][2]);
                split_tf32(As[r0 + 8][c + 4], ah[mt][3], al[mt][3]);
            }
#pragma unroll
            for (int mt = 0; mt < 2; mt++)
#pragma unroll
                for (int nt = 0; nt < 4; nt++) {
                    mma8(acc[mt][nt], al[mt], bh[nt]);
                    mma8(acc[mt][nt], ah[mt], bl[nt]);
                    mma8(acc[mt][nt], ah[mt], bh[nt]);
                }
        }
        __syncthreads();
        if (k0 < 7) {
#pragma unroll
            for (int j = 0; j < 4; j++) *(float4*)&As[ar0 + 32 * j][ac4] = pa[j];
            *(float4*)&Bs[br][bc4]      = pb[0];
            *(float4*)&Bs[16 + br][bc4] = pb[1];
            __syncthreads();
        }
    }

#pragma unroll
    for (int mt = 0; mt < 2; mt++) {
        int gr0 = brow + wm * 32 + mt * 16 + q;
#pragma unroll
        for (int nt = 0; nt < 4; nt++) {
            int gc = bcol + wn * 32 + nt * 8 + 2 * tq;
            float bx = 0.f, by = 0.f;
            if (BIAS) { bx = bias[gc]; by = bias[gc + 1]; }
            float2 v0 = make_float2(acc[mt][nt][0] + bx, acc[mt][nt][1] + by);
            float2 v1 = make_float2(acc[mt][nt][2] + bx, acc[mt][nt][3] + by);
            if (RELU) {
                v0.x = fmaxf(v0.x, 0.f); v0.y = fmaxf(v0.y, 0.f);
                v1.x = fmaxf(v1.x, 0.f); v1.y = fmaxf(v1.y, 0.f);
            }
            if (gr0 < M)     *(float2*)(C + gr0 * 256 + gc)       = v0;
            if (gr0 + 8 < M) *(float2*)(C + (gr0 + 8) * 256 + gc) = v1;
        }
    }
}

// ---------------- per-node attention logits (warp per node) ----------------
__global__ void node_att(const float* __restrict__ att_src,
                         const float* __restrict__ att_dst, int n) {
    int warp = (blockIdx.x * blockDim.x + threadIdx.x) >> 5;
    int lane = threadIdx.x & 31;
    if (warp >= n) return;
    const int i = warp;
    const float4* xp = (const float4*)(g_xp + i * 256);
    float4 v0 = xp[lane * 2];
    float4 v1 = xp[lane * 2 + 1];
    const float4* as4 = (const float4*)att_src;
    const float4* ad4 = (const float4*)att_dst;
    float4 s0 = as4[lane * 2], s1 = as4[lane * 2 + 1];
    float4 d0 = ad4[lane * 2], d1 = ad4[lane * 2 + 1];
    float s = v0.x * s0.x + v0.y * s0.y + v0.z * s0.z + v0.w * s0.w
            + v1.x * s1.x + v1.y * s1.y + v1.z * s1.z + v1.w * s1.w;
    float d = v0.x * d0.x + v0.y * d0.y + v0.z * d0.z + v0.w * d0.w
            + v1.x * d1.x + v1.y * d1.y + v1.z * d1.z + v1.w * d1.w;
    s += __shfl_xor_sync(0xffffffffu, s, 1);
    s += __shfl_xor_sync(0xffffffffu, s, 2);
    d += __shfl_xor_sync(0xffffffffu, d, 1);
    d += __shfl_xor_sync(0xffffffffu, d, 2);
    if ((lane & 3) == 0) {
        int h = lane >> 2;
        g_asrc[i * 8 + h] = s;
        g_adst[i * 8 + h] = d;
    }
}

// ---------------- CSR build: degree count ----------------
__global__ void deg_count(const int* __restrict__ ei, int E) {
    int e = blockIdx.x * blockDim.x + threadIdx.x;
    if (e >= E) return;
    atomicAdd(&g_deg[ei[E + e]], 1);
}

// ---------------- multi-block scan (2 kernels) ----------------
__global__ void scan_part(int n) {
    __shared__ int wsum[32];
    int tid = threadIdx.x, lane = tid & 31, wid = tid >> 5;
    int n4 = (n + 3) >> 2;
    int f = blockIdx.x * 1024 + tid;
    int4 v = make_int4(0, 0, 0, 0);
    if (f < n4) {
        if (f * 4 + 3 < n) v = ((const int4*)g_deg)[f];
        else {
            if (f * 4 + 0 < n) v.x = g_deg[f * 4 + 0];
            if (f * 4 + 1 < n) v.y = g_deg[f * 4 + 1];
            if (f * 4 + 2 < n) v.z = g_deg[f * 4 + 2];
        }
    }
    int tsum = v.x + v.y + v.z + v.w;
    int x = tsum;
#pragma unroll
    for (int o = 1; o < 32; o <<= 1) {
        int t = __shfl_up_sync(0xffffffffu, x, o);
        if (lane >= o) x += t;
    }
    if (lane == 31) wsum[wid] = x;
    __syncthreads();
    if (wid == 0) {
        int w = wsum[lane];
#pragma unroll
        for (int o = 1; o < 32; o <<= 1) {
            int t = __shfl_up_sync(0xffffffffu, w, o);
            if (lane >= o) w += t;
        }
        wsum[lane] = w;
    }
    __syncthreads();
    int excl = (wid ? wsum[wid - 1] : 0) + x - tsum;
    int4 o4;
    o4.x = excl;
    o4.y = o4.x + v.x;
    o4.z = o4.y + v.y;
    o4.w = o4.z + v.z;
    if (f < n4) {
        if (f * 4 + 3 < n) ((int4*)g_off)[f] = o4;
        else {
            if (f * 4 + 0 < n) g_off[f * 4 + 0] = o4.x;
            if (f * 4 + 1 < n) g_off[f * 4 + 1] = o4.y;
            if (f * 4 + 2 < n) g_off[f * 4 + 2] = o4.z;
        }
    }
    if (tid == 0) g_bsum[blockIdx.x] = wsum[31];
}

// adds exclusive prefix of block sums (computed in-kernel, ≤32 blocks)
__global__ void scan_add(int n) {
    __shared__ int s_add;
    int tid = threadIdx.x;
    if (tid < 32) {
        int v = (tid < (int)blockIdx.x) ? g_bsum[tid] : 0;
#pragma unroll
        for (int o = 16; o; o >>= 1) v += __shfl_xor_sync(0xffffffffu, v, o);
        if (tid == 0) s_add = v;
    }
    __syncthreads();
    int add = s_add;
    int n4 = (n + 3) >> 2;
    int f = blockIdx.x * 1024 + tid;
    if (f >= n4) return;
    if (f * 4 + 3 < n) {
        int4 o = ((const int4*)g_off)[f];
        o.x += add; o.y += add; o.z += add; o.w += add;
        ((int4*)g_off)[f] = o;
        ((int4*)g_cur)[f] = o;
    } else {
#pragma unroll
        for (int j = 0; j < 3; j++)
            if (f * 4 + j < n) {
                int o = g_off[f * 4 + j] + add;
                g_off[f * 4 + j] = o;
                g_cur[f * 4 + j] = o;
            }
    }
}

// ---------------- CSR build: fill source lists ----------------
__global__ void csr_fill(const int* __restrict__ ei, int E) {
    int e = blockIdx.x * blockDim.x + threadIdx.x;
    if (e >= E) return;
    int s = ei[e];
    int d = ei[E + e];
    int pos = atomicAdd(&g_cur[d], 1);
    g_srcl[pos] = s;
}

// ---------------- fused gather: softmax + aggregate + bias + residual + LN ----------------
__global__ void gat_gather(const float* __restrict__ x,
                           const float* __restrict__ bias,
                           const float* __restrict__ gamma,
                           const float* __restrict__ beta, int n) {
    int warp = (blockIdx.x * blockDim.x + threadIdx.x) >> 5;
    int lane = threadIdx.x & 31;
    if (warp >= n) return;
    const int i  = warp;
    const int h0 = lane >> 3;
    const int h1 = 4 + h0;

    float4 acc0 = {0.f, 0.f, 0.f, 0.f};
    float4 acc1 = {0.f, 0.f, 0.f, 0.f};
    float  den  = 0.f;
    float  adst = (lane < 8) ? g_adst[i * 8 + lane] : 0.f;

    const int start = g_off[i];
    const int deg   = g_deg[i];

    int e = 0;
    for (; e + 2 <= deg; e += 2) {
        int s0 = g_srcl[start + e];
        int s1 = g_srcl[start + e + 1];
        float ex0 = 0.f, ex1 = 0.f;
        if (lane < 8) {
            ex0 = __expf(leaky(g_asrc[s0 * 8 + lane] + adst));
            ex1 = __expf(leaky(g_asrc[s1 * 8 + lane] + adst));
            den += ex0 + ex1;
        }
        float a00 = __shfl_sync(0xffffffffu, ex0, h0);
        float a01 = __shfl_sync(0xffffffffu, ex0, h1);
        float a10 = __shfl_sync(0xffffffffu, ex1, h0);
        float a11 = __shfl_sync(0xffffffffu, ex1, h1);
        const float4* xs0 = (const float4*)(g_xp + s0 * 256);
        const float4* xs1 = (const float4*)(g_xp + s1 * 256);
        float4 u0 = xs0[lane], u1 = xs0[32 + lane];
        float4 w0 = xs1[lane], w1 = xs1[32 + lane];
        acc0.x = fmaf(a00, u0.x, acc0.x); acc0.y = fmaf(a00, u0.y, acc0.y);
        acc0.z = fmaf(a00, u0.z, acc0.z); acc0.w = fmaf(a00, u0.w, acc0.w);
        acc1.x = fmaf(a01, u1.x, acc1.x); acc1.y = fmaf(a01, u1.y, acc1.y);
        acc1.z = fmaf(a01, u1.z, acc1.z); acc1.w = fmaf(a01, u1.w, acc1.w);
        acc0.x = fmaf(a10, w0.x, acc0.x); acc0.y = fmaf(a10, w0.y, acc0.y);
        acc0.z = fmaf(a10, w0.z, acc0.z); acc0.w = fmaf(a10, w0.w, acc0.w);
        acc1.x = fmaf(a11, w1.x, acc1.x); acc1.y = fmaf(a11, w1.y, acc1.y);
        acc1.z = fmaf(a11, w1.z, acc1.z); acc1.w = fmaf(a11, w1.w, acc1.w);
    }
    for (; e < deg; e++) {
        int s = g_srcl[start + e];
        float ex = 0.f;
        if (lane < 8) {
            ex = __expf(leaky(g_asrc[s * 8 + lane] + adst));
            den += ex;
        }
        float e0 = __shfl_sync(0xffffffffu, ex, h0);
        float e1 = __shfl_sync(0xffffffffu, ex, h1);
        const float4* xs = (const float4*)(g_xp + s * 256);
        float4 v0 = xs[lane], v1 = xs[32 + lane];
        acc0.x = fmaf(e0, v0.x, acc0.x); acc0.y = fmaf(e0, v0.y, acc0.y);
        acc0.z = fmaf(e0, v0.z, acc0.z); acc0.w = fmaf(e0, v0.w, acc0.w);
        acc1.x = fmaf(e1, v1.x, acc1.x); acc1.y = fmaf(e1, v1.y, acc1.y);
        acc1.z = fmaf(e1, v1.z, acc1.z); acc1.w = fmaf(e1, v1.w, acc1.w);
    }

    // self loop
    {
        float ex = 0.f;
        if (lane < 8) {
            ex = __expf(leaky(g_asrc[i * 8 + lane] + adst));
            den += ex;
        }
        float e0 = __shfl_sync(0xffffffffu, ex, h0);
        float e1 = __shfl_sync(0xffffffffu, ex, h1);
        const float4* xs = (const float4*)(g_xp + i * 256);
        float4 v0 = xs[lane], v1 = xs[32 + lane];
        acc0.x = fmaf(e0, v0.x, acc0.x); acc0.y = fmaf(e0, v0.y, acc0.y);
        acc0.z = fmaf(e0, v0.z, acc0.z); acc0.w = fmaf(e0, v0.w, acc0.w);
        acc1.x = fmaf(e1, v1.x, acc1.x); acc1.y = fmaf(e1, v1.y, acc1.y);
        acc1.z = fmaf(e1, v1.z, acc1.z); acc1.w = fmaf(e1, v1.w, acc1.w);
    }

    float inv0 = 1.f / (__shfl_sync(0xffffffffu, den, h0) + 1e-16f);
    float inv1 = 1.f / (__shfl_sync(0xffffffffu, den, h1) + 1e-16f);

    const float4* xr = (const float4*)(x + i * 256);
    const float4* bi = (const float4*)bias;
    float4 xv0 = xr[lane], xv1 = xr[32 + lane];
    float4 b0  = bi[lane], b1  = bi[32 + lane];
    float r[8];
    r[0] = fmaf(acc0.x, inv0, b0.x) + xv0.x;
    r[1] = fmaf(acc0.y, inv0, b0.y) + xv0.y;
    r[2] = fmaf(acc0.z, inv0, b0.z) + xv0.z;
    r[3] = fmaf(acc0.w, inv0, b0.w) + xv0.w;
    r[4] = fmaf(acc1.x, inv1, b1.x) + xv1.x;
    r[5] = fmaf(acc1.y, inv1, b1.y) + xv1.y;
    r[6] = fmaf(acc1.z, inv1, b1.z) + xv1.z;
    r[7] = fmaf(acc1.w, inv1, b1.w) + xv1.w;

    float s = r[0] + r[1] + r[2] + r[3] + r[4] + r[5] + r[6] + r[7];
#pragma unroll
    for (int o = 16; o; o >>= 1) s += __shfl_xor_sync(0xffffffffu, s, o);
    float mu = s * (1.0f / 256.0f);
    float c[8], v2 = 0.f;
#pragma unroll
    for (int k = 0; k < 8; k++) { c[k] = r[k] - mu; v2 = fmaf(c[k], c[k], v2); }
#pragma unroll
    for (int o = 16; o; o >>= 1) v2 += __shfl_xor_sync(0xffffffffu, v2, o);
    float rstd = rsqrtf(v2 * (1.0f / 256.0f) + 1e-5f);

    const float4* gp = (const float4*)gamma;
    const float4* bp = (const float4*)beta;
    float4 g0 = gp[lane], g1 = gp[32 + lane];
    float4 p0 = bp[lane], p1 = bp[32 + lane];
    float4 o0, o1;
    o0.x = fmaf(c[0] * rstd, g0.x, p0.x);
    o0.y = fmaf(c[1] * rstd, g0.y, p0.y);
    o0.z = fmaf(c[2] * rstd, g0.z, p0.z);
    o0.w = fmaf(c[3] * rstd, g0.w, p0.w);
    o1.x = fmaf(c[4] * rstd, g1.x, p1.x);
    o1.y = fmaf(c[5] * rstd, g1.y, p1.y);
    o1.z = fmaf(c[6] * rstd, g1.z, p1.z);
    o1.w = fmaf(c[7] * rstd, g1.w, p1.w);
    float4* out = (float4*)(g_hn + i * 256);
    out[lane]      = o0;
    out[32 + lane] = o1;
}

// ---------------- launch ----------------
extern "C" void kernel_launch(void* const* d_in, const int* in_sizes, int n_in,
                              void* d_out, int out_size) {
    const float* x       = (const float*)d_in[0];
    const int*   ei      = (const int*)d_in[1];   // int32 (JAX x64 disabled)
    const float* W       = (const float*)d_in[3];
    const float* att_src = (const float*)d_in[4];
    const float* att_dst = (const float*)d_in[5];
    const float* bias    = (const float*)d_in[6];
    const float* ln_g    = (const float*)d_in[7];
    const float* ln_b    = (const float*)d_in[8];
    const float* W1      = (const float*)d_in[9];
    const float* b1      = (const float*)d_in[10];
    const float* W2      = (const float*)d_in[11];
    const float* b2      = (const float*)d_in[12];

    const int n = in_sizes[0] / DD;       // 50000
    const int E = in_sizes[1] / 2;        // 800000

    float *xp, *hn, *hid;
    int   *deg;
    cudaGetSymbolAddress((void**)&xp,  g_xp);
    cudaGetSymbolAddress((void**)&hn,  g_hn);
    cudaGetSymbolAddress((void**)&hid, g_hid);
    cudaGetSymbolAddress((void**)&deg, g_deg);

    // persistent side stream + fork/join events (created on first call,
    // which is the uncaptured correctness run; capture replays record/wait)
    static cudaStream_t s2 = nullptr;
    static cudaEvent_t ev_fork = nullptr, ev_join = nullptr;
    if (!s2) {
        cudaStreamCreateWithFlags(&s2, cudaStreamNonBlocking);
        cudaEventCreateWithFlags(&ev_fork, cudaEventDisableTiming);
        cudaEventCreateWithFlags(&ev_join, cudaEventDisableTiming);
    }

    dim3 gg((n + 127) / 128, 4);
    const int n4 = (n + 3) >> 2;
    const int nscan = (n4 + 1023) / 1024;

    // fork: CSR chain on s2, GEMM1 + node_att on default
    cudaEventRecord(ev_fork, 0);
    cudaStreamWaitEvent(s2, ev_fork, 0);

    cudaMemsetAsync(deg, 0, n * sizeof(int), s2);
    deg_count<<<(E + 511) / 512, 512, 0, s2>>>(ei, E);
    scan_part<<<nscan, 1024, 0, s2>>>(n);
    scan_add <<<nscan, 1024, 0, s2>>>(n);
    csr_fill <<<(E + 255) / 256, 256, 0, s2>>>(ei, E);
    cudaEventRecord(ev_join, s2);

    gemm_tc<false, false><<<gg, 256>>>(x, W, nullptr, xp, n);
    node_att<<<(n * 32 + 255) / 256, 256>>>(att_src, att_dst, n);

    // join
    cudaStreamWaitEvent(0, ev_join, 0);

    // fused softmax + gather + bias + residual + LN
    gat_gather<<<(n * 32 + 255) / 256, 256>>>(x, bias, ln_g, ln_b, n);
    // FFN
    gemm_tc<true,  true><<<gg, 256>>>(hn,  W1, b1, hid, n);
    gemm_tc<false, true><<<gg, 256>>>(hid, W2, b2, (float*)d_out, n);
}

// round 7
// speedup vs baseline: 5.1272x; 1.2218x over previous
#include <cuda_runtime.h>
#include <cuda_bf16.h>

// ---------------- problem constants ----------------
#define DD 256
#define HH 8
#define HDD 32
#define N_MAX 50048
#define E_MAX 800000
#define NEG_SLOPE 0.2f

// ---------------- device scratch ----------------
__device__ __align__(256) float g_xp  [N_MAX * DD];
__device__ __align__(256) float g_asrc[N_MAX * HH];
__device__ __align__(256) float g_adst[N_MAX * HH];
__device__ __align__(256) float g_hn  [N_MAX * DD];
__device__ __align__(256) float g_hid [N_MAX * DD];
__device__ __align__(256) int   g_deg [N_MAX];
__device__ __align__(256) int   g_off [N_MAX];
__device__ __align__(256) int   g_cur [N_MAX];
__device__ __align__(256) int   g_srcl[E_MAX];
__device__ int g_bsum[64];

__device__ __forceinline__ float leaky(float v) {
    return v > 0.f ? v : NEG_SLOPE * v;
}

// ---------------- bf16-split helpers ----------------
// hi halves of two floats packed to bf16x2 (x -> low half)
__device__ __forceinline__ unsigned pack_hi(float x, float y) {
    unsigned r;
    asm("prmt.b32 %0, %1, %2, 0x7632;"
        : "=r"(r) : "r"(__float_as_uint(x)), "r"(__float_as_uint(y)));
    return r;
}
// residuals (a - trunc_bf16(a)) of two floats packed to bf16x2 (x -> low half)
__device__ __forceinline__ unsigned pack_lo(float x, float y) {
    float hx = __uint_as_float(__float_as_uint(x) & 0xffff0000u);
    float hy = __uint_as_float(__float_as_uint(y) & 0xffff0000u);
    float lx = x - hx, ly = y - hy;
    unsigned r;
    asm("cvt.rn.bf16x2.f32 %0, %1, %2;" : "=r"(r) : "f"(ly), "f"(lx));
    return r;
}

__device__ __forceinline__ void mma16(float* c, const unsigned* a, const unsigned* b) {
    asm("mma.sync.aligned.m16n8k16.row.col.f32.bf16.bf16.f32 "
        "{%0,%1,%2,%3}, {%4,%5,%6,%7}, {%8,%9}, {%0,%1,%2,%3};"
        : "+f"(c[0]), "+f"(c[1]), "+f"(c[2]), "+f"(c[3])
        : "r"(a[0]), "r"(a[1]), "r"(a[2]), "r"(a[3]), "r"(b[0]), "r"(b[1]));
}

// ---------------- tensor-core GEMM (3xBF16 split, m16n8k16) ----------------
// block: 256 threads = 8 warps (4m x 2n), tile 128 x 64; warp tile 32 x 32
template <bool RELU, bool BIAS>
__global__ __launch_bounds__(256)
void gemm_tc(const float* __restrict__ A, const float* __restrict__ B,
             const float* __restrict__ bias, float* __restrict__ C, int M) {
    __shared__ float As[128][36];
    __shared__ float Bs[32][68];
    const int tid  = threadIdx.x;
    const int lane = tid & 31;
    const int warp = tid >> 5;
    const int wm   = warp & 3;
    const int wn   = warp >> 2;
    const int brow = blockIdx.x * 128;
    const int bcol = blockIdx.y * 64;
    const int q    = lane >> 2;
    const int tq   = lane & 3;

    const int ar0 = tid >> 3;
    const int ac4 = (tid & 7) * 4;
    const int br  = tid >> 4;
    const int bc4 = (tid & 15) * 4;

    float acc[2][4][4];
#pragma unroll
    for (int mt = 0; mt < 2; mt++)
#pragma unroll
        for (int nt = 0; nt < 4; nt++)
#pragma unroll
            for (int k = 0; k < 4; k++) acc[mt][nt][k] = 0.f;

    float4 pa[4], pb[2];

#pragma unroll
    for (int j = 0; j < 4; j++) {
        int gr = brow + ar0 + 32 * j;
        pa[j] = (gr < M) ? *(const float4*)(A + gr * 256 + ac4)
                         : make_float4(0.f, 0.f, 0.f, 0.f);
    }
    pb[0] = *(const float4*)(B + br * 256 + bcol + bc4);
    pb[1] = *(const float4*)(B + (16 + br) * 256 + bcol + bc4);
#pragma unroll
    for (int j = 0; j < 4; j++) *(float4*)&As[ar0 + 32 * j][ac4] = pa[j];
    *(float4*)&Bs[br][bc4]      = pb[0];
    *(float4*)&Bs[16 + br][bc4] = pb[1];
    __syncthreads();

    for (int k0 = 0; k0 < 8; k0++) {
        if (k0 < 7) {
            int kb = (k0 + 1) * 32;
#pragma unroll
            for (int j = 0; j < 4; j++) {
                int gr = brow + ar0 + 32 * j;
                pa[j] = (gr < M) ? *(const float4*)(A + gr * 256 + kb + ac4)
                                 : make_float4(0.f, 0.f, 0.f, 0.f);
            }
            pb[0] = *(const float4*)(B + (kb + br) * 256 + bcol + bc4);
            pb[1] = *(const float4*)(B + (kb + 16 + br) * 256 + bcol + bc4);
        }

#pragma unroll
        for (int kk = 0; kk < 2; kk++) {
            const int kb = kk * 16;
            unsigned bh[4][2], bl[4][2];
#pragma unroll
            for (int nt = 0; nt < 4; nt++) {
                int col = wn * 32 + nt * 8 + q;
                int r0  = kb + 2 * tq;
                float x0 = Bs[r0][col],     x1 = Bs[r0 + 1][col];
                float x2 = Bs[r0 + 8][col], x3 = Bs[r0 + 9][col];
                bh[nt][0] = pack_hi(x0, x1); bl[nt][0] = pack_lo(x0, x1);
                bh[nt][1] = pack_hi(x2, x3); bl[nt][1] = pack_lo(x2, x3);
            }
            unsigned ah[2][4], al[2][4];
#pragma unroll
            for (int mt = 0; mt < 2; mt++) {
                int r0 = wm * 32 + mt * 16 + q;
                int c  = kb + 2 * tq;
                float2 p0 = *(float2*)&As[r0][c];
                float2 p1 = *(float2*)&As[r0 + 8][c];
                float2 p2 = *(float2*)&As[r0][c + 8];
                float2 p3 = *(float2*)&As[r0 + 8][c + 8];
                ah[mt][0] = pack_hi(p0.x, p0.y); al[mt][0] = pack_lo(p0.x, p0.y);
                ah[mt][1] = pack_hi(p1.x, p1.y); al[mt][1] = pack_lo(p1.x, p1.y);
                ah[mt][2] = pack_hi(p2.x, p2.y); al[mt][2] = pack_lo(p2.x, p2.y);
                ah[mt][3] = pack_hi(p3.x, p3.y); al[mt][3] = pack_lo(p3.x, p3.y);
            }
#pragma unroll
            for (int mt = 0; mt < 2; mt++)
#pragma unroll
                for (int nt = 0; nt < 4; nt++) {
                    mma16(acc[mt][nt], al[mt], bh[nt]);
                    mma16(acc[mt][nt], ah[mt], bl[nt]);
                    mma16(acc[mt][nt], ah[mt], bh[nt]);
                }
        }
        __syncthreads();
        if (k0 < 7) {
#pragma unroll
            for (int j = 0; j < 4; j++) *(float4*)&As[ar0 + 32 * j][ac4] = pa[j];
            *(float4*)&Bs[br][bc4]      = pb[0];
            *(float4*)&Bs[16 + br][bc4] = pb[1];
            __syncthreads();
        }
    }

#pragma unroll
    for (int mt = 0; mt < 2; mt++) {
        int gr0 = brow + wm * 32 + mt * 16 + q;
#pragma unroll
        for (int nt = 0; nt < 4; nt++) {
            int gc = bcol + wn * 32 + nt * 8 + 2 * tq;
            float bx = 0.f, by = 0.f;
            if (BIAS) { bx = bias[gc]; by = bias[gc + 1]; }
            float2 v0 = make_float2(acc[mt][nt][0] + bx, acc[mt][nt][1] + by);
            float2 v1 = make_float2(acc[mt][nt][2] + bx, acc[mt][nt][3] + by);
            if (RELU) {
                v0.x = fmaxf(v0.x, 0.f); v0.y = fmaxf(v0.y, 0.f);
                v1.x = fmaxf(v1.x, 0.f); v1.y = fmaxf(v1.y, 0.f);
            }
            if (gr0 < M)     *(float2*)(C + gr0 * 256 + gc)       = v0;
            if (gr0 + 8 < M) *(float2*)(C + (gr0 + 8) * 256 + gc) = v1;
        }
    }
}

// ---------------- per-node attention logits (warp per node) ----------------
__global__ void node_att(const float* __restrict__ att_src,
                         const float* __restrict__ att_dst, int n) {
    int warp = (blockIdx.x * blockDim.x + threadIdx.x) >> 5;
    int lane = threadIdx.x & 31;
    if (warp >= n) return;
    const int i = warp;
    const float4* xp = (const float4*)(g_xp + i * 256);
    float4 v0 = xp[lane * 2];
    float4 v1 = xp[lane * 2 + 1];
    const float4* as4 = (const float4*)att_src;
    const float4* ad4 = (const float4*)att_dst;
    float4 s0 = as4[lane * 2], s1 = as4[lane * 2 + 1];
    float4 d0 = ad4[lane * 2], d1 = ad4[lane * 2 + 1];
    float s = v0.x * s0.x + v0.y * s0.y + v0.z * s0.z + v0.w * s0.w
            + v1.x * s1.x + v1.y * s1.y + v1.z * s1.z + v1.w * s1.w;
    float d = v0.x * d0.x + v0.y * d0.y + v0.z * d0.z + v0.w * d0.w
            + v1.x * d1.x + v1.y * d1.y + v1.z * d1.z + v1.w * d1.w;
    s += __shfl_xor_sync(0xffffffffu, s, 1);
    s += __shfl_xor_sync(0xffffffffu, s, 2);
    d += __shfl_xor_sync(0xffffffffu, d, 1);
    d += __shfl_xor_sync(0xffffffffu, d, 2);
    if ((lane & 3) == 0) {
        int h = lane >> 2;
        g_asrc[i * 8 + h] = s;
        g_adst[i * 8 + h] = d;
    }
}

// ---------------- CSR build ----------------
__global__ void deg_count(const int* __restrict__ ei, int E) {
    int e = blockIdx.x * blockDim.x + threadIdx.x;
    if (e >= E) return;
    atomicAdd(&g_deg[ei[E + e]], 1);
}

__global__ void scan_part(int n) {
    __shared__ int wsum[32];
    int tid = threadIdx.x, lane = tid & 31, wid = tid >> 5;
    int n4 = (n + 3) >> 2;
    int f = blockIdx.x * 1024 + tid;
    int4 v = make_int4(0, 0, 0, 0);
    if (f < n4) {
        if (f * 4 + 3 < n) v = ((const int4*)g_deg)[f];
        else {
            if (f * 4 + 0 < n) v.x = g_deg[f * 4 + 0];
            if (f * 4 + 1 < n) v.y = g_deg[f * 4 + 1];
            if (f * 4 + 2 < n) v.z = g_deg[f * 4 + 2];
        }
    }
    int tsum = v.x + v.y + v.z + v.w;
    int x = tsum;
#pragma unroll
    for (int o = 1; o < 32; o <<= 1) {
        int t = __shfl_up_sync(0xffffffffu, x, o);
        if (lane >= o) x += t;
    }
    if (lane == 31) wsum[wid] = x;
    __syncthreads();
    if (wid == 0) {
        int w = wsum[lane];
#pragma unroll
        for (int o = 1; o < 32; o <<= 1) {
            int t = __shfl_up_sync(0xffffffffu, w, o);
            if (lane >= o) w += t;
        }
        wsum[lane] = w;
    }
    __syncthreads();
    int excl = (wid ? wsum[wid - 1] : 0) + x - tsum;
    int4 o4;
    o4.x = excl;
    o4.y = o4.x + v.x;
    o4.z = o4.y + v.y;
    o4.w = o4.z + v.z;
    if (f < n4) {
        if (f * 4 + 3 < n) ((int4*)g_off)[f] = o4;
        else {
            if (f * 4 + 0 < n) g_off[f * 4 + 0] = o4.x;
            if (f * 4 + 1 < n) g_off[f * 4 + 1] = o4.y;
            if (f * 4 + 2 < n) g_off[f * 4 + 2] = o4.z;
        }
    }
    if (tid == 0) g_bsum[blockIdx.x] = wsum[31];
}

__global__ void scan_add(int n) {
    __shared__ int s_add;
    int tid = threadIdx.x;
    if (tid < 32) {
        int v = (tid < (int)blockIdx.x) ? g_bsum[tid] : 0;
#pragma unroll
        for (int o = 16; o; o >>= 1) v += __shfl_xor_sync(0xffffffffu, v, o);
        if (tid == 0) s_add = v;
    }
    __syncthreads();
    int add = s_add;
    int n4 = (n + 3) >> 2;
    int f = blockIdx.x * 1024 + tid;
    if (f >= n4) return;
    if (f * 4 + 3 < n) {
        int4 o = ((const int4*)g_off)[f];
        o.x += add; o.y += add; o.z += add; o.w += add;
        ((int4*)g_off)[f] = o;
        ((int4*)g_cur)[f] = o;
    } else {
#pragma unroll
        for (int j = 0; j < 3; j++)
            if (f * 4 + j < n) {
                int o = g_off[f * 4 + j] + add;
                g_off[f * 4 + j] = o;
                g_cur[f * 4 + j] = o;
            }
    }
}

__global__ void csr_fill(const int* __restrict__ ei, int E) {
    int e = blockIdx.x * blockDim.x + threadIdx.x;
    if (e >= E) return;
    int s = ei[e];
    int d = ei[E + e];
    int pos = atomicAdd(&g_cur[d], 1);
    g_srcl[pos] = s;
}

// ---------------- fused gather: softmax + aggregate + bias + residual + LN ----------------
__global__ void gat_gather(const float* __restrict__ x,
                           const float* __restrict__ bias,
                           const float* __restrict__ gamma,
                           const float* __restrict__ beta, int n) {
    int warp = (blockIdx.x * blockDim.x + threadIdx.x) >> 5;
    int lane = threadIdx.x & 31;
    if (warp >= n) return;
    const int i  = warp;
    const int h0 = lane >> 3;
    const int h1 = 4 + h0;

    float4 acc0 = {0.f, 0.f, 0.f, 0.f};
    float4 acc1 = {0.f, 0.f, 0.f, 0.f};
    float  den  = 0.f;
    float  adst = (lane < 8) ? g_adst[i * 8 + lane] : 0.f;

    const int start = g_off[i];
    const int deg   = g_deg[i];

    int e = 0;
    for (; e + 4 <= deg; e += 4) {
        int s0 = g_srcl[start + e];
        int s1 = g_srcl[start + e + 1];
        int s2 = g_srcl[start + e + 2];
        int s3 = g_srcl[start + e + 3];
        float ex0 = 0.f, ex1 = 0.f, ex2 = 0.f, ex3 = 0.f;
        if (lane < 8) {
            float l0 = g_asrc[s0 * 8 + lane];
            float l1 = g_asrc[s1 * 8 + lane];
            float l2 = g_asrc[s2 * 8 + lane];
            float l3 = g_asrc[s3 * 8 + lane];
            ex0 = __expf(leaky(l0 + adst));
            ex1 = __expf(leaky(l1 + adst));
            ex2 = __expf(leaky(l2 + adst));
            ex3 = __expf(leaky(l3 + adst));
            den += (ex0 + ex1) + (ex2 + ex3);
        }
        const float4* xs0 = (const float4*)(g_xp + s0 * 256);
        const float4* xs1 = (const float4*)(g_xp + s1 * 256);
        const float4* xs2 = (const float4*)(g_xp + s2 * 256);
        const float4* xs3 = (const float4*)(g_xp + s3 * 256);
        float4 u0 = xs0[lane], u1 = xs0[32 + lane];
        float4 w0 = xs1[lane], w1 = xs1[32 + lane];
        float4 y0 = xs2[lane], y1 = xs2[32 + lane];
        float4 z0 = xs3[lane], z1 = xs3[32 + lane];
        float a00 = __shfl_sync(0xffffffffu, ex0, h0);
        float a01 = __shfl_sync(0xffffffffu, ex0, h1);
        float a10 = __shfl_sync(0xffffffffu, ex1, h0);
        float a11 = __shfl_sync(0xffffffffu, ex1, h1);
        float a20 = __shfl_sync(0xffffffffu, ex2, h0);
        float a21 = __shfl_sync(0xffffffffu, ex2, h1);
        float a30 = __shfl_sync(0xffffffffu, ex3, h0);
        float a31 = __shfl_sync(0xffffffffu, ex3, h1);
        acc0.x = fmaf(a00, u0.x, acc0.x); acc0.y = fmaf(a00, u0.y, acc0.y);
        acc0.z = fmaf(a00, u0.z, acc0.z); acc0.w = fmaf(a00, u0.w, acc0.w);
        acc1.x = fmaf(a01, u1.x, acc1.x); acc1.y = fmaf(a01, u1.y, acc1.y);
        acc1.z = fmaf(a01, u1.z, acc1.z); acc1.w = fmaf(a01, u1.w, acc1.w);
        acc0.x = fmaf(a10, w0.x, acc0.x); acc0.y = fmaf(a10, w0.y, acc0.y);
        acc0.z = fmaf(a10, w0.z, acc0.z); acc0.w = fmaf(a10, w0.w, acc0.w);
        acc1.x = fmaf(a11, w1.x, acc1.x); acc1.y = fmaf(a11, w1.y, acc1.y);
        acc1.z = fmaf(a11, w1.z, acc1.z); acc1.w = fmaf(a11, w1.w, acc1.w);
        acc0.x = fmaf(a20, y0.x, acc0.x); acc0.y = fmaf(a20, y0.y, acc0.y);
        acc0.z = fmaf(a20, y0.z, acc0.z); acc0.w = fmaf(a20, y0.w, acc0.w);
        acc1.x = fmaf(a21, y1.x, acc1.x); acc1.y = fmaf(a21, y1.y, acc1.y);
        acc1.z = fmaf(a21, y1.z, acc1.z); acc1.w = fmaf(a21, y1.w, acc1.w);
        acc0.x = fmaf(a30, z0.x, acc0.x); acc0.y = fmaf(a30, z0.y, acc0.y);
        acc0.z = fmaf(a30, z0.z, acc0.z); acc0.w = fmaf(a30, z0.w, acc0.w);
        acc1.x = fmaf(a31, z1.x, acc1.x); acc1.y = fmaf(a31, z1.y, acc1.y);
        acc1.z = fmaf(a31, z1.z, acc1.z); acc1.w = fmaf(a31, z1.w, acc1.w);
    }
    for (; e < deg; e++) {
        int s = g_srcl[start + e];
        float ex = 0.f;
        if (lane < 8) {
            ex = __expf(leaky(g_asrc[s * 8 + lane] + adst));
            den += ex;
        }
        float e0 = __shfl_sync(0xffffffffu, ex, h0);
        float e1 = __shfl_sync(0xffffffffu, ex, h1);
        const float4* xs = (const float4*)(g_xp + s * 256);
        float4 v0 = xs[lane], v1 = xs[32 + lane];
        acc0.x = fmaf(e0, v0.x, acc0.x); acc0.y = fmaf(e0, v0.y, acc0.y);
        acc0.z = fmaf(e0, v0.z, acc0.z); acc0.w = fmaf(e0, v0.w, acc0.w);
        acc1.x = fmaf(e1, v1.x, acc1.x); acc1.y = fmaf(e1, v1.y, acc1.y);
        acc1.z = fmaf(e1, v1.z, acc1.z); acc1.w = fmaf(e1, v1.w, acc1.w);
    }

    // self loop
    {
        float ex = 0.f;
        if (lane < 8) {
            ex = __expf(leaky(g_asrc[i * 8 + lane] + adst));
            den += ex;
        }
        float e0 = __shfl_sync(0xffffffffu, ex, h0);
        float e1 = __shfl_sync(0xffffffffu, ex, h1);
        const float4* xs = (const float4*)(g_xp + i * 256);
        float4 v0 = xs[lane], v1 = xs[32 + lane];
        acc0.x = fmaf(e0, v0.x, acc0.x); acc0.y = fmaf(e0, v0.y, acc0.y);
        acc0.z = fmaf(e0, v0.z, acc0.z); acc0.w = fmaf(e0, v0.w, acc0.w);
        acc1.x = fmaf(e1, v1.x, acc1.x); acc1.y = fmaf(e1, v1.y, acc1.y);
        acc1.z = fmaf(e1, v1.z, acc1.z); acc1.w = fmaf(e1, v1.w, acc1.w);
    }

    float inv0 = 1.f / (__shfl_sync(0xffffffffu, den, h0) + 1e-16f);
    float inv1 = 1.f / (__shfl_sync(0xffffffffu, den, h1) + 1e-16f);

    const float4* xr = (const float4*)(x + i * 256);
    const float4* bi = (const float4*)bias;
    float4 xv0 = xr[lane], xv1 = xr[32 + lane];
    float4 b0  = bi[lane], b1  = bi[32 + lane];
    float r[8];
    r[0] = fmaf(acc0.x, inv0, b0.x) + xv0.x;
    r[1] = fmaf(acc0.y, inv0, b0.y) + xv0.y;
    r[2] = fmaf(acc0.z, inv0, b0.z) + xv0.z;
    r[3] = fmaf(acc0.w, inv0, b0.w) + xv0.w;
    r[4] = fmaf(acc1.x, inv1, b1.x) + xv1.x;
    r[5] = fmaf(acc1.y, inv1, b1.y) + xv1.y;
    r[6] = fmaf(acc1.z, inv1, b1.z) + xv1.z;
    r[7] = fmaf(acc1.w, inv1, b1.w) + xv1.w;

    float s = r[0] + r[1] + r[2] + r[3] + r[4] + r[5] + r[6] + r[7];
#pragma unroll
    for (int o = 16; o; o >>= 1) s += __shfl_xor_sync(0xffffffffu, s, o);
    float mu = s * (1.0f / 256.0f);
    float c[8], v2 = 0.f;
#pragma unroll
    for (int k = 0; k < 8; k++) { c[k] = r[k] - mu; v2 = fmaf(c[k], c[k], v2); }
#pragma unroll
    for (int o = 16; o; o >>= 1) v2 += __shfl_xor_sync(0xffffffffu, v2, o);
    float rstd = rsqrtf(v2 * (1.0f / 256.0f) + 1e-5f);

    const float4* gp = (const float4*)gamma;
    const float4* bp = (const float4*)beta;
    float4 g0 = gp[lane], g1 = gp[32 + lane];
    float4 p0 = bp[lane], p1 = bp[32 + lane];
    float4 o0, o1;
    o0.x = fmaf(c[0] * rstd, g0.x, p0.x);
    o0.y = fmaf(c[1] * rstd, g0.y, p0.y);
    o0.z = fmaf(c[2] * rstd, g0.z, p0.z);
    o0.w = fmaf(c[3] * rstd, g0.w, p0.w);
    o1.x = fmaf(c[4] * rstd, g1.x, p1.x);
    o1.y = fmaf(c[5] * rstd, g1.y, p1.y);
    o1.z = fmaf(c[6] * rstd, g1.z, p1.z);
    o1.w = fmaf(c[7] * rstd, g1.w, p1.w);
    float4* out = (float4*)(g_hn + i * 256);
    out[lane]      = o0;
    out[32 + lane] = o1;
}

// ---------------- launch ----------------
extern "C" void kernel_launch(void* const* d_in, const int* in_sizes, int n_in,
                              void* d_out, int out_size) {
    const float* x       = (const float*)d_in[0];
    const int*   ei      = (const int*)d_in[1];
    const float* W       = (const float*)d_in[3];
    const float* att_src = (const float*)d_in[4];
    const float* att_dst = (const float*)d_in[5];
    const float* bias    = (const float*)d_in[6];
    const float* ln_g    = (const float*)d_in[7];
    const float* ln_b    = (const float*)d_in[8];
    const float* W1      = (const float*)d_in[9];
    const float* b1      = (const float*)d_in[10];
    const float* W2      = (const float*)d_in[11];
    const float* b2      = (const float*)d_in[12];

    const int n = in_sizes[0] / DD;
    const int E = in_sizes[1] / 2;

    float *xp, *hn, *hid;
    int   *deg;
    cudaGetSymbolAddress((void**)&xp,  g_xp);
    cudaGetSymbolAddress((void**)&hn,  g_hn);
    cudaGetSymbolAddress((void**)&hid, g_hid);
    cudaGetSymbolAddress((void**)&deg, g_deg);

    static cudaStream_t s2 = nullptr;
    static cudaEvent_t ev_fork = nullptr, ev_join = nullptr;
    if (!s2) {
        cudaStreamCreateWithFlags(&s2, cudaStreamNonBlocking);
        cudaEventCreateWithFlags(&ev_fork, cudaEventDisableTiming);
        cudaEventCreateWithFlags(&ev_join, cudaEventDisableTiming);
    }

    dim3 gg((n + 127) / 128, 4);
    const int n4 = (n + 3) >> 2;
    const int nscan = (n4 + 1023) / 1024;

    cudaEventRecord(ev_fork, 0);
    cudaStreamWaitEvent(s2, ev_fork, 0);

    cudaMemsetAsync(deg, 0, n * sizeof(int), s2);
    deg_count<<<(E + 511) / 512, 512, 0, s2>>>(ei, E);
    scan_part<<<nscan, 1024, 0, s2>>>(n);
    scan_add <<<nscan, 1024, 0, s2>>>(n);
    csr_fill <<<(E + 255) / 256, 256, 0, s2>>>(ei, E);
    cudaEventRecord(ev_join, s2);

    gemm_tc<false, false><<<gg, 256>>>(x, W, nullptr, xp, n);
    node_att<<<(n * 32 + 255) / 256, 256>>>(att_src, att_dst, n);

    cudaStreamWaitEvent(0, ev_join, 0);

    gat_gather<<<(n * 32 + 255) / 256, 256>>>(x, bias, ln_g, ln_b, n);
    gemm_tc<true,  true><<<gg, 256>>>(hn,  W1, b1, hid, n);
    gemm_tc<false, true><<<gg, 256>>>(hid, W2, b2, (float*)d_out, n);
}